// round 2
// baseline (speedup 1.0000x reference)
#include <cuda_runtime.h>
#include <math.h>

#define BB 512
#define NSV 128
#define NTRK 512
#define KK 8
#define HH 16

#define POS_INF_F (__int_as_float(0x7f800000))
#define NEG_INF_F (__int_as_float(0xff800000))

__device__ __forceinline__ float elu_f(float x) {
    return x > 0.0f ? x : expm1f(x);
}

__global__ __launch_bounds__(512, 1)
void fused_gnn_kernel(
    const float* __restrict__ x_sv,   // (B*NSV, 2)
    const float* __restrict__ x_trk,  // (B*NTRK, 8)
    const float* __restrict__ W1s, const float* __restrict__ b1s,
    const float* __restrict__ W2s, const float* __restrict__ b2s,
    const float* __restrict__ W1t, const float* __restrict__ b1t,
    const float* __restrict__ W2t, const float* __restrict__ b2t,
    const float* __restrict__ We,  const float* __restrict__ be,
    const float* __restrict__ Wo,  const float* __restrict__ bo,
    float* __restrict__ out, int out_size)
{
    __shared__ __align__(16) float s_sv[NSV][HH];     // sv features
    __shared__ __align__(16) float s_proj[NSV][20];   // sv @ WeB (padded stride vs bank conflicts)
    __shared__ float s_ssq[NSV];
    __shared__ __align__(16) float s_W1t[8][HH];
    __shared__ __align__(16) float s_W2t[HH][HH];
    __shared__ __align__(16) float s_WeD[HH][HH];     // WeA - WeB
    __shared__ float s_b1t[HH], s_b2t[HH], s_be[HH], s_Wo[HH];
    __shared__ float s_bo;
    __shared__ float s_warpsum[16];

    const int b   = blockIdx.x;
    const int tid = threadIdx.x;

    // ---- stage weights into SMEM (all threads, strided) ----
    for (int i = tid; i < 8 * HH; i += 512) s_W1t[i / HH][i % HH] = W1t[i];
    for (int i = tid; i < HH * HH; i += 512) s_W2t[i / HH][i % HH] = W2t[i];
    for (int i = tid; i < HH * HH; i += 512) {
        int j = i / HH, h = i % HH;
        s_WeD[j][h] = We[j * HH + h] - We[(HH + j) * HH + h];
    }
    if (tid < HH) {
        s_b1t[tid] = b1t[tid];
        s_b2t[tid] = b2t[tid];
        s_be[tid]  = be[tid];
        s_Wo[tid]  = Wo[tid];
    }
    if (tid == 0) s_bo = bo[0];

    // ---- per-batch SV features + precomputed projections (threads 0..127) ----
    if (tid < NSV) {
        const int s = tid;
        const float x0 = x_sv[(size_t)(b * NSV + s) * 2 + 0];
        const float x1 = x_sv[(size_t)(b * NSV + s) * 2 + 1];
        float h1[HH];
        #pragma unroll
        for (int h = 0; h < HH; ++h)
            h1[h] = elu_f(fmaf(x0, W1s[0 * HH + h], fmaf(x1, W1s[1 * HH + h], b1s[h])));
        float f[HH];
        float sq = 0.0f;
        #pragma unroll
        for (int h = 0; h < HH; ++h) {
            float acc = b2s[h];
            #pragma unroll
            for (int j = 0; j < HH; ++j) acc = fmaf(h1[j], W2s[j * HH + h], acc);
            f[h] = acc;
            sq = fmaf(acc, acc, sq);
            s_sv[s][h] = acc;
        }
        s_ssq[s] = sq;
        // proj[s][h] = sum_j f[j] * WeB[j][h]   (WeB = rows H..2H-1 of We)
        #pragma unroll
        for (int h = 0; h < HH; ++h) {
            float acc = 0.0f;
            #pragma unroll
            for (int j = 0; j < HH; ++j) acc = fmaf(f[j], We[(HH + j) * HH + h], acc);
            s_proj[s][h] = acc;
        }
    }
    __syncthreads();

    // ---- per-track pipeline: one thread per track ----
    const int t = tid;  // NTRK == blockDim.x == 512
    const float4* xt4 = reinterpret_cast<const float4*>(x_trk + (size_t)(b * NTRK + t) * 8);
    const float4 xa = xt4[0];
    const float4 xb = xt4[1];
    const float xv[8] = {xa.x, xa.y, xa.z, xa.w, xb.x, xb.y, xb.z, xb.w};

    // trk MLP: elu(x @ W1t + b1t) @ W2t + b2t
    float h1[HH];
    #pragma unroll
    for (int h = 0; h < HH; ++h) {
        float acc = s_b1t[h];
        #pragma unroll
        for (int j = 0; j < 8; ++j) acc = fmaf(xv[j], s_W1t[j][h], acc);
        h1[h] = elu_f(acc);
    }
    float tf[HH];
    #pragma unroll
    for (int h = 0; h < HH; ++h) {
        float acc = s_b2t[h];
        #pragma unroll
        for (int j = 0; j < HH; ++j) acc = fmaf(h1[j], s_W2t[j][h], acc);
        tf[h] = acc;
    }

    // tpart[h] = be[h] + sum_j tf[j] * (WeA - WeB)[j][h]
    float tpart[HH];
    #pragma unroll
    for (int h = 0; h < HH; ++h) {
        float acc = s_be[h];
        #pragma unroll
        for (int j = 0; j < HH; ++j) acc = fmaf(tf[j], s_WeD[j][h], acc);
        tpart[h] = acc;
    }

    // ---- kNN: top-8 smallest (s_sq - 2*dot); constant t_sq shift preserves order ----
    float bd[KK];
    int   bi[KK];
    #pragma unroll
    for (int k = 0; k < KK; ++k) { bd[k] = POS_INF_F; bi[k] = 0; }

    for (int s = 0; s < NSV; ++s) {
        const float4* sv4 = reinterpret_cast<const float4*>(s_sv[s]);
        const float4 a0 = sv4[0], a1 = sv4[1], a2 = sv4[2], a3 = sv4[3];
        float dot = tf[0] * a0.x;
        dot = fmaf(tf[1],  a0.y, dot);
        dot = fmaf(tf[2],  a0.z, dot);
        dot = fmaf(tf[3],  a0.w, dot);
        dot = fmaf(tf[4],  a1.x, dot);
        dot = fmaf(tf[5],  a1.y, dot);
        dot = fmaf(tf[6],  a1.z, dot);
        dot = fmaf(tf[7],  a1.w, dot);
        dot = fmaf(tf[8],  a2.x, dot);
        dot = fmaf(tf[9],  a2.y, dot);
        dot = fmaf(tf[10], a2.z, dot);
        dot = fmaf(tf[11], a2.w, dot);
        dot = fmaf(tf[12], a3.x, dot);
        dot = fmaf(tf[13], a3.y, dot);
        dot = fmaf(tf[14], a3.z, dot);
        dot = fmaf(tf[15], a3.w, dot);
        float key = fmaf(-2.0f, dot, s_ssq[s]);
        if (key < bd[KK - 1]) {
            bd[KK - 1] = key;
            bi[KK - 1] = s;
            #pragma unroll
            for (int j = KK - 1; j > 0; --j) {
                if (bd[j] < bd[j - 1]) {
                    float td = bd[j]; bd[j] = bd[j - 1]; bd[j - 1] = td;
                    int   ii = bi[j]; bi[j] = bi[j - 1]; bi[j - 1] = ii;
                }
            }
        }
    }

    // ---- feats[h] = tpart[h] + max_k proj[bi[k]][h]; out = sigmoid(feats @ Wo + bo) ----
    float pm[HH];
    #pragma unroll
    for (int h = 0; h < HH; ++h) pm[h] = NEG_INF_F;
    #pragma unroll
    for (int k = 0; k < KK; ++k) {
        const float4* pr = reinterpret_cast<const float4*>(s_proj[bi[k]]);
        const float4 p0 = pr[0], p1 = pr[1], p2 = pr[2], p3 = pr[3];
        pm[0]  = fmaxf(pm[0],  p0.x); pm[1]  = fmaxf(pm[1],  p0.y);
        pm[2]  = fmaxf(pm[2],  p0.z); pm[3]  = fmaxf(pm[3],  p0.w);
        pm[4]  = fmaxf(pm[4],  p1.x); pm[5]  = fmaxf(pm[5],  p1.y);
        pm[6]  = fmaxf(pm[6],  p1.z); pm[7]  = fmaxf(pm[7],  p1.w);
        pm[8]  = fmaxf(pm[8],  p2.x); pm[9]  = fmaxf(pm[9],  p2.y);
        pm[10] = fmaxf(pm[10], p2.z); pm[11] = fmaxf(pm[11], p2.w);
        pm[12] = fmaxf(pm[12], p3.x); pm[13] = fmaxf(pm[13], p3.y);
        pm[14] = fmaxf(pm[14], p3.z); pm[15] = fmaxf(pm[15], p3.w);
    }
    float acc = s_bo;
    #pragma unroll
    for (int h = 0; h < HH; ++h) acc = fmaf(tpart[h] + pm[h], s_Wo[h], acc);
    const float o = 1.0f / (1.0f + expf(-acc));

    // ---- block mean over 512 tracks ----
    float v = o;
    #pragma unroll
    for (int off = 16; off > 0; off >>= 1) v += __shfl_xor_sync(0xFFFFFFFFu, v, off);
    const int warp = tid >> 5;
    const int lane = tid & 31;
    if (lane == 0) s_warpsum[warp] = v;
    __syncthreads();
    if (tid == 0) {
        float ssum = 0.0f;
        #pragma unroll
        for (int w = 0; w < 16; ++w) ssum += s_warpsum[w];
        out[b] = ssum * (1.0f / (float)NTRK);
        if (BB + b < out_size) out[BB + b] = (float)b;
    }
}

extern "C" void kernel_launch(void* const* d_in, const int* in_sizes, int n_in,
                              void* d_out, int out_size) {
    const float* x_sv = (const float*)d_in[0];
    const float* x_trk = (const float*)d_in[1];
    // d_in[2] = batch_sv, d_in[3] = batch_trk : deterministic repeats, unused
    const float* W1s = (const float*)d_in[4];
    const float* b1s = (const float*)d_in[5];
    const float* W2s = (const float*)d_in[6];
    const float* b2s = (const float*)d_in[7];
    const float* W1t = (const float*)d_in[8];
    const float* b1t = (const float*)d_in[9];
    const float* W2t = (const float*)d_in[10];
    const float* b2t = (const float*)d_in[11];
    const float* We  = (const float*)d_in[12];
    const float* be  = (const float*)d_in[13];
    const float* Wo  = (const float*)d_in[14];
    const float* bo  = (const float*)d_in[15];
    float* out = (float*)d_out;

    fused_gnn_kernel<<<BB, 512>>>(x_sv, x_trk,
                                  W1s, b1s, W2s, b2s,
                                  W1t, b1t, W2t, b2t,
                                  We, be, Wo, bo,
                                  out, out_size);
}

// round 3
// speedup vs baseline: 1.6682x; 1.6682x over previous
#include <cuda_runtime.h>
#include <math.h>

typedef unsigned long long ull;

#define BB 512
#define NSV 128
#define NTRK 512
#define KK 8
#define HH 16

__device__ __forceinline__ ull pack2(float lo, float hi) {
    ull r; asm("mov.b64 %0, {%1, %2};" : "=l"(r) : "f"(lo), "f"(hi)); return r;
}
__device__ __forceinline__ void unpack2(ull v, float& lo, float& hi) {
    asm("mov.b64 {%0, %1}, %2;" : "=f"(lo), "=f"(hi) : "l"(v));
}
__device__ __forceinline__ ull fma2(ull a, ull b, ull c) {
    ull d; asm("fma.rn.f32x2 %0, %1, %2, %3;" : "=l"(d) : "l"(a), "l"(b), "l"(c)); return d;
}
__device__ __forceinline__ ull mul2(ull a, ull b) {
    ull d; asm("mul.rn.f32x2 %0, %1, %2;" : "=l"(d) : "l"(a), "l"(b)); return d;
}
__device__ __forceinline__ float elu_f(float x) { return x > 0.0f ? x : expm1f(x); }

__global__ __launch_bounds__(512, 1)
void fused_gnn_kernel(
    const float* __restrict__ x_sv,   // (B*NSV, 2)
    const float* __restrict__ x_trk,  // (B*NTRK, 8)
    const float* __restrict__ W1s, const float* __restrict__ b1s,
    const float* __restrict__ W2s, const float* __restrict__ b2s,
    const float* __restrict__ W1t, const float* __restrict__ b1t,
    const float* __restrict__ W2t, const float* __restrict__ b2t,
    const float* __restrict__ We,  const float* __restrict__ be,
    const float* __restrict__ Wo,  const float* __restrict__ bo,
    float* __restrict__ out, int out_size)
{
    __shared__ __align__(16) float s_sv[NSV][HH];     // sv features (uniform-row reads in knn loop)
    __shared__ __align__(16) float s_proj[NSV][20];   // sv @ WeB, padded stride
    __shared__ __align__(16) ull   s_ssq2[NSV];       // pack2(|sv|^2, 0)
    __shared__ __align__(16) float s_h1[NSV][HH];     // sv hidden layer
    __shared__ __align__(16) float s_W1t[8][HH];
    __shared__ __align__(16) float s_W2t[HH][HH];
    __shared__ __align__(16) float s_WeD[HH][HH];     // WeA - WeB
    __shared__ __align__(16) float s_W2s[HH][HH];
    __shared__ __align__(16) float s_WeB[HH][HH];
    __shared__ __align__(16) float s_b1t[HH], s_b2t[HH], s_be[HH], s_Wo[HH];
    __shared__ float s_bo;
    __shared__ float s_warpsum[16];

    const int b   = blockIdx.x;
    const int tid = threadIdx.x;

    // ---- stage weights into SMEM ----
    for (int i = tid; i < 8 * HH; i += 512) s_W1t[i / HH][i % HH] = W1t[i];
    for (int i = tid; i < HH * HH; i += 512) {
        int j = i / HH, h = i % HH;
        s_W2t[j][h] = W2t[i];
        s_W2s[j][h] = W2s[i];
        float wa = We[j * HH + h];
        float wb = We[(HH + j) * HH + h];
        s_WeB[j][h] = wb;
        s_WeD[j][h] = wa - wb;
    }
    if (tid < HH) {
        s_b1t[tid] = b1t[tid];
        s_b2t[tid] = b2t[tid];
        s_be[tid]  = be[tid];
        s_Wo[tid]  = Wo[tid];
    }
    if (tid == 0) s_bo = bo[0];

    // ---- SV prep, parallel over 512 threads: thread = (sv s, h-quad q) ----
    const int sp = tid >> 2;
    const int q  = tid & 3;
    {
        // stage A1: hidden layer h1 for 4 h's
        const float x0 = x_sv[(size_t)(b * NSV + sp) * 2 + 0];
        const float x1 = x_sv[(size_t)(b * NSV + sp) * 2 + 1];
        #pragma unroll
        for (int i = 0; i < 4; ++i) {
            int h = 4 * q + i;
            float pre = fmaf(x0, W1s[h], fmaf(x1, W1s[HH + h], b1s[h]));
            s_h1[sp][h] = elu_f(pre);
        }
    }
    __syncthreads();
    {
        // stage A2: sv features f = h1 @ W2s + b2s (4 columns per thread)
        float a0 = b2s[4 * q + 0], a1 = b2s[4 * q + 1];
        float a2 = b2s[4 * q + 2], a3 = b2s[4 * q + 3];
        #pragma unroll
        for (int j = 0; j < HH; ++j) {
            float hj = s_h1[sp][j];
            a0 = fmaf(hj, s_W2s[j][4 * q + 0], a0);
            a1 = fmaf(hj, s_W2s[j][4 * q + 1], a1);
            a2 = fmaf(hj, s_W2s[j][4 * q + 2], a2);
            a3 = fmaf(hj, s_W2s[j][4 * q + 3], a3);
        }
        s_sv[sp][4 * q + 0] = a0; s_sv[sp][4 * q + 1] = a1;
        s_sv[sp][4 * q + 2] = a2; s_sv[sp][4 * q + 3] = a3;
    }
    __syncthreads();
    {
        // stage B: proj = f @ WeB (4 cols per thread); q==0 also |f|^2
        float a0 = 0.f, a1 = 0.f, a2 = 0.f, a3 = 0.f, ssq = 0.f;
        #pragma unroll
        for (int j = 0; j < HH; ++j) {
            float fj = s_sv[sp][j];
            a0 = fmaf(fj, s_WeB[j][4 * q + 0], a0);
            a1 = fmaf(fj, s_WeB[j][4 * q + 1], a1);
            a2 = fmaf(fj, s_WeB[j][4 * q + 2], a2);
            a3 = fmaf(fj, s_WeB[j][4 * q + 3], a3);
            if (q == 0) ssq = fmaf(fj, fj, ssq);
        }
        s_proj[sp][4 * q + 0] = a0; s_proj[sp][4 * q + 1] = a1;
        s_proj[sp][4 * q + 2] = a2; s_proj[sp][4 * q + 3] = a3;
        if (q == 0) s_ssq2[sp] = pack2(ssq, 0.0f);
    }
    __syncthreads();

    // ---- per-track pipeline: one thread per track ----
    const float4* xt4 = reinterpret_cast<const float4*>(x_trk + (size_t)(b * NTRK + tid) * 8);
    const float4 xa = xt4[0];
    const float4 xb = xt4[1];
    const float xv[8] = {xa.x, xa.y, xa.z, xa.w, xb.x, xb.y, xb.z, xb.w};

    // trk hidden layer (scalar; rows of W1t vectorize to LDS.128)
    float h1[HH];
    #pragma unroll
    for (int h = 0; h < HH; ++h) h1[h] = s_b1t[h];
    #pragma unroll
    for (int j = 0; j < 8; ++j) {
        float xj = xv[j];
        #pragma unroll
        for (int h = 0; h < HH; ++h) h1[h] = fmaf(xj, s_W1t[j][h], h1[h]);
    }
    #pragma unroll
    for (int h = 0; h < HH; ++h) h1[h] = elu_f(h1[h]);

    // tf = h1 @ W2t + b2t (f32x2, output pairs)
    ull tf2[8];
    #pragma unroll
    for (int p = 0; p < 8; ++p) tf2[p] = *reinterpret_cast<const ull*>(&s_b2t[2 * p]);
    #pragma unroll
    for (int j = 0; j < HH; ++j) {
        ull hb = pack2(h1[j], h1[j]);
        const ulonglong2* row = reinterpret_cast<const ulonglong2*>(s_W2t[j]);
        ulonglong2 r0 = row[0], r1 = row[1];
        tf2[0] = fma2(hb, r0.x, tf2[0]); tf2[1] = fma2(hb, r0.y, tf2[1]);
        tf2[2] = fma2(hb, r1.x, tf2[2]); tf2[3] = fma2(hb, r1.y, tf2[3]);
        ulonglong2 r2 = row[2], r3 = row[3];
        tf2[4] = fma2(hb, r2.x, tf2[4]); tf2[5] = fma2(hb, r2.y, tf2[5]);
        tf2[6] = fma2(hb, r3.x, tf2[6]); tf2[7] = fma2(hb, r3.y, tf2[7]);
    }
    float tf[HH];
    #pragma unroll
    for (int p = 0; p < 8; ++p) unpack2(tf2[p], tf[2 * p], tf[2 * p + 1]);

    // tpart = be + tf @ (WeA - WeB)  (f32x2, output pairs)
    ull tp2[8];
    #pragma unroll
    for (int p = 0; p < 8; ++p) tp2[p] = *reinterpret_cast<const ull*>(&s_be[2 * p]);
    #pragma unroll
    for (int j = 0; j < HH; ++j) {
        ull tb = pack2(tf[j], tf[j]);
        const ulonglong2* row = reinterpret_cast<const ulonglong2*>(s_WeD[j]);
        ulonglong2 r0 = row[0], r1 = row[1];
        tp2[0] = fma2(tb, r0.x, tp2[0]); tp2[1] = fma2(tb, r0.y, tp2[1]);
        tp2[2] = fma2(tb, r1.x, tp2[2]); tp2[3] = fma2(tb, r1.y, tp2[3]);
        ulonglong2 r2 = row[2], r3 = row[3];
        tp2[4] = fma2(tb, r2.x, tp2[4]); tp2[5] = fma2(tb, r2.y, tp2[5]);
        tp2[6] = fma2(tb, r3.x, tp2[6]); tp2[7] = fma2(tb, r3.y, tp2[7]);
    }
    float tpart[HH];
    #pragma unroll
    for (int p = 0; p < 8; ++p) unpack2(tp2[p], tpart[2 * p], tpart[2 * p + 1]);

    // pre-scaled -2*tf pairs for the distance keys
    ull tfm2[8];
    {
        ull n2 = pack2(-2.0f, -2.0f);
        #pragma unroll
        for (int p = 0; p < 8; ++p) tfm2[p] = mul2(tf2[p], n2);
    }

    // ---- kNN: branch-free top-8 on packed (orderable-key | sv-index) uint32 ----
    unsigned int A[KK];
    #pragma unroll
    for (int k = 0; k < KK; ++k) A[k] = 0xFFFFFFFFu;

    #pragma unroll 2
    for (int s = 0; s < NSV; ++s) {
        const ulonglong2* sp2 = reinterpret_cast<const ulonglong2*>(s_sv[s]);
        ulonglong2 v0 = sp2[0], v1 = sp2[1];
        ull acc = fma2(tfm2[0], v0.x, s_ssq2[s]);
        acc = fma2(tfm2[1], v0.y, acc);
        acc = fma2(tfm2[2], v1.x, acc);
        acc = fma2(tfm2[3], v1.y, acc);
        ulonglong2 v2 = sp2[2], v3 = sp2[3];
        acc = fma2(tfm2[4], v2.x, acc);
        acc = fma2(tfm2[5], v2.y, acc);
        acc = fma2(tfm2[6], v3.x, acc);
        acc = fma2(tfm2[7], v3.y, acc);
        float lo, hi;
        unpack2(acc, lo, hi);
        float key = lo + hi;                       // = |sv|^2 - 2*(tf . sv)
        unsigned int u = __float_as_uint(key);
        u ^= (unsigned int)(((int)u >> 31)) | 0x80000000u;  // monotone float->uint
        unsigned int t = (u & 0xFFFFFF80u) | (unsigned int)s;
        #pragma unroll
        for (int j = 0; j < KK; ++j) {
            unsigned int lo_ = min(A[j], t);
            t = max(A[j], t);
            A[j] = lo_;
        }
    }

    // ---- feats[h] = tpart[h] + max_k proj[nbr_k][h] ----
    float pm[HH];
    #pragma unroll
    for (int h = 0; h < HH; ++h) pm[h] = __int_as_float(0xff800000);
    #pragma unroll
    for (int k = 0; k < KK; ++k) {
        int idx = (int)(A[k] & 0x7Fu);
        const float4* pr = reinterpret_cast<const float4*>(s_proj[idx]);
        const float4 p0 = pr[0], p1 = pr[1], p2 = pr[2], p3 = pr[3];
        pm[0]  = fmaxf(pm[0],  p0.x); pm[1]  = fmaxf(pm[1],  p0.y);
        pm[2]  = fmaxf(pm[2],  p0.z); pm[3]  = fmaxf(pm[3],  p0.w);
        pm[4]  = fmaxf(pm[4],  p1.x); pm[5]  = fmaxf(pm[5],  p1.y);
        pm[6]  = fmaxf(pm[6],  p1.z); pm[7]  = fmaxf(pm[7],  p1.w);
        pm[8]  = fmaxf(pm[8],  p2.x); pm[9]  = fmaxf(pm[9],  p2.y);
        pm[10] = fmaxf(pm[10], p2.z); pm[11] = fmaxf(pm[11], p2.w);
        pm[12] = fmaxf(pm[12], p3.x); pm[13] = fmaxf(pm[13], p3.y);
        pm[14] = fmaxf(pm[14], p3.z); pm[15] = fmaxf(pm[15], p3.w);
    }
    float acc = s_bo;
    #pragma unroll
    for (int h = 0; h < HH; ++h) acc = fmaf(tpart[h] + pm[h], s_Wo[h], acc);
    const float o = 1.0f / (1.0f + expf(-acc));

    // ---- block mean over 512 tracks ----
    float v = o;
    #pragma unroll
    for (int off = 16; off > 0; off >>= 1) v += __shfl_xor_sync(0xFFFFFFFFu, v, off);
    const int warp = tid >> 5;
    const int lane = tid & 31;
    if (lane == 0) s_warpsum[warp] = v;
    __syncthreads();
    if (tid == 0) {
        float ssum = 0.0f;
        #pragma unroll
        for (int w = 0; w < 16; ++w) ssum += s_warpsum[w];
        out[b] = ssum * (1.0f / (float)NTRK);
        if (BB + b < out_size) out[BB + b] = (float)b;
    }
}

extern "C" void kernel_launch(void* const* d_in, const int* in_sizes, int n_in,
                              void* d_out, int out_size) {
    const float* x_sv = (const float*)d_in[0];
    const float* x_trk = (const float*)d_in[1];
    // d_in[2] = batch_sv, d_in[3] = batch_trk : deterministic repeats, unused
    const float* W1s = (const float*)d_in[4];
    const float* b1s = (const float*)d_in[5];
    const float* W2s = (const float*)d_in[6];
    const float* b2s = (const float*)d_in[7];
    const float* W1t = (const float*)d_in[8];
    const float* b1t = (const float*)d_in[9];
    const float* W2t = (const float*)d_in[10];
    const float* b2t = (const float*)d_in[11];
    const float* We  = (const float*)d_in[12];
    const float* be  = (const float*)d_in[13];
    const float* Wo  = (const float*)d_in[14];
    const float* bo  = (const float*)d_in[15];
    float* out = (float*)d_out;

    fused_gnn_kernel<<<BB, 512>>>(x_sv, x_trk,
                                  W1s, b1s, W2s, b2s,
                                  W1t, b1t, W2t, b2t,
                                  We, be, Wo, bo,
                                  out, out_size);
}

// round 4
// speedup vs baseline: 1.8540x; 1.1114x over previous
#include <cuda_runtime.h>
#include <math.h>

typedef unsigned long long ull;

#define BB 512
#define NSV 128
#define NTRK 512
#define KK 8
#define HH 16
#define TPB 256

__device__ __forceinline__ ull pack2(float lo, float hi) {
    ull r; asm("mov.b64 %0, {%1, %2};" : "=l"(r) : "f"(lo), "f"(hi)); return r;
}
__device__ __forceinline__ void unpack2(ull v, float& lo, float& hi) {
    asm("mov.b64 {%0, %1}, %2;" : "=f"(lo), "=f"(hi) : "l"(v));
}
__device__ __forceinline__ ull fma2(ull a, ull b, ull c) {
    ull d; asm("fma.rn.f32x2 %0, %1, %2, %3;" : "=l"(d) : "l"(a), "l"(b), "l"(c)); return d;
}
__device__ __forceinline__ ull mul2(ull a, ull b) {
    ull d; asm("mul.rn.f32x2 %0, %1, %2;" : "=l"(d) : "l"(a), "l"(b)); return d;
}
__device__ __forceinline__ float elu_f(float x) { return x > 0.0f ? x : expm1f(x); }

__global__ __launch_bounds__(TPB, 2)
void fused_gnn_kernel(
    const float* __restrict__ x_sv,   // (B*NSV, 2)
    const float* __restrict__ x_trk,  // (B*NTRK, 8)
    const float* __restrict__ W1s, const float* __restrict__ b1s,
    const float* __restrict__ W2s, const float* __restrict__ b2s,
    const float* __restrict__ W1t, const float* __restrict__ b1t,
    const float* __restrict__ W2t, const float* __restrict__ b2t,
    const float* __restrict__ We,  const float* __restrict__ be,
    const float* __restrict__ Wo,  const float* __restrict__ bo,
    float* __restrict__ out, int out_size)
{
    __shared__ __align__(16) float s_sv[NSV][HH];
    __shared__ float s_ssq[NSV];
    __shared__ __align__(16) float s_proj[NSV][20];
    __shared__ __align__(16) float s_h1[NSV][HH];
    __shared__ __align__(16) float s_W1t[8][HH];
    __shared__ __align__(16) float s_W2t[HH][HH];
    __shared__ __align__(16) float s_W2s[HH][HH];
    __shared__ __align__(16) float s_WeB[HH][HH];
    __shared__ __align__(16) float s_b1t[HH], s_b2t[HH], s_wv[HH], s_Wo[HH];
    __shared__ float s_const;
    __shared__ float s_warpsum[8];

    const int b   = blockIdx.x;
    const int tid = threadIdx.x;

    // ---- stage weights ----
    for (int i = tid; i < 8 * HH; i += TPB) s_W1t[i / HH][i % HH] = W1t[i];
    for (int i = tid; i < HH * HH; i += TPB) {
        int j = i / HH, h = i % HH;
        s_W2t[j][h] = W2t[i];
        s_W2s[j][h] = W2s[i];
        s_WeB[j][h] = We[(HH + j) * HH + h];
    }
    if (tid < HH) {
        s_b1t[tid] = b1t[tid];
        s_b2t[tid] = b2t[tid];
        s_Wo[tid]  = Wo[tid];
        // wv[j] = sum_h (WeA - WeB)[j][h] * Wo[h]
        float acc = 0.0f;
        #pragma unroll
        for (int h = 0; h < HH; ++h)
            acc += (We[tid * HH + h] - We[(HH + tid) * HH + h]) * Wo[h];
        s_wv[tid] = acc;
    }
    if (tid == 0) {
        float c = bo[0];
        #pragma unroll
        for (int h = 0; h < HH; ++h) c += be[h] * Wo[h];
        s_const = c;
    }

    // ---- SV prep: 2 threads per SV, 8 columns each ----
    const int sp = tid >> 1;
    const int hc = (tid & 1) * 8;
    {
        const float x0 = x_sv[(size_t)(b * NSV + sp) * 2 + 0];
        const float x1 = x_sv[(size_t)(b * NSV + sp) * 2 + 1];
        #pragma unroll
        for (int i = 0; i < 8; ++i) {
            int h = hc + i;
            s_h1[sp][h] = elu_f(fmaf(x0, W1s[h], fmaf(x1, W1s[HH + h], b1s[h])));
        }
    }
    __syncthreads();
    {
        float a[8];
        #pragma unroll
        for (int i = 0; i < 8; ++i) a[i] = b2s[hc + i];
        #pragma unroll
        for (int j = 0; j < HH; ++j) {
            float hj = s_h1[sp][j];
            #pragma unroll
            for (int i = 0; i < 8; ++i) a[i] = fmaf(hj, s_W2s[j][hc + i], a[i]);
        }
        #pragma unroll
        for (int i = 0; i < 8; ++i) s_sv[sp][hc + i] = a[i];
    }
    __syncthreads();
    {
        float a[8];
        #pragma unroll
        for (int i = 0; i < 8; ++i) a[i] = 0.0f;
        float sq = 0.0f;
        #pragma unroll
        for (int j = 0; j < HH; ++j) {
            float fj = s_sv[sp][j];
            #pragma unroll
            for (int i = 0; i < 8; ++i) a[i] = fmaf(fj, s_WeB[j][hc + i], a[i]);
            if (hc == 0) sq = fmaf(fj, fj, sq);
        }
        #pragma unroll
        for (int i = 0; i < 8; ++i) s_proj[sp][hc + i] = a[i];
        if (hc == 0) s_ssq[sp] = sq;
    }
    __syncthreads();

    // ---- 2 tracks per thread ----
    const float4* xt0 = reinterpret_cast<const float4*>(x_trk + (size_t)(b * NTRK + tid) * 8);
    const float4* xt1 = reinterpret_cast<const float4*>(x_trk + (size_t)(b * NTRK + tid + TPB) * 8);
    const float4 xa0 = xt0[0], xb0 = xt0[1];
    const float4 xa1 = xt1[0], xb1 = xt1[1];
    const float xv0[8] = {xa0.x, xa0.y, xa0.z, xa0.w, xb0.x, xb0.y, xb0.z, xb0.w};
    const float xv1[8] = {xa1.x, xa1.y, xa1.z, xa1.w, xb1.x, xb1.y, xb1.z, xb1.w};

    // hidden layer for both (f32x2), sharing weight-row loads
    ull h1a2[8], h1b2[8];
    #pragma unroll
    for (int p = 0; p < 8; ++p) {
        ull bb = *reinterpret_cast<const ull*>(&s_b1t[2 * p]);
        h1a2[p] = bb; h1b2[p] = bb;
    }
    #pragma unroll
    for (int j = 0; j < 8; ++j) {
        const ulonglong2* row = reinterpret_cast<const ulonglong2*>(s_W1t[j]);
        ulonglong2 r0 = row[0], r1 = row[1], r2 = row[2], r3 = row[3];
        ull xj0 = pack2(xv0[j], xv0[j]);
        ull xj1 = pack2(xv1[j], xv1[j]);
        h1a2[0] = fma2(xj0, r0.x, h1a2[0]); h1a2[1] = fma2(xj0, r0.y, h1a2[1]);
        h1a2[2] = fma2(xj0, r1.x, h1a2[2]); h1a2[3] = fma2(xj0, r1.y, h1a2[3]);
        h1a2[4] = fma2(xj0, r2.x, h1a2[4]); h1a2[5] = fma2(xj0, r2.y, h1a2[5]);
        h1a2[6] = fma2(xj0, r3.x, h1a2[6]); h1a2[7] = fma2(xj0, r3.y, h1a2[7]);
        h1b2[0] = fma2(xj1, r0.x, h1b2[0]); h1b2[1] = fma2(xj1, r0.y, h1b2[1]);
        h1b2[2] = fma2(xj1, r1.x, h1b2[2]); h1b2[3] = fma2(xj1, r1.y, h1b2[3]);
        h1b2[4] = fma2(xj1, r2.x, h1b2[4]); h1b2[5] = fma2(xj1, r2.y, h1b2[5]);
        h1b2[6] = fma2(xj1, r3.x, h1b2[6]); h1b2[7] = fma2(xj1, r3.y, h1b2[7]);
    }
    float ha[HH], hb[HH];
    #pragma unroll
    for (int p = 0; p < 8; ++p) {
        unpack2(h1a2[p], ha[2 * p], ha[2 * p + 1]);
        unpack2(h1b2[p], hb[2 * p], hb[2 * p + 1]);
    }
    #pragma unroll
    for (int h = 0; h < HH; ++h) { ha[h] = elu_f(ha[h]); hb[h] = elu_f(hb[h]); }

    // tf = h1 @ W2t + b2t for both tracks
    ull tfa2[8], tfb2[8];
    #pragma unroll
    for (int p = 0; p < 8; ++p) {
        ull bb = *reinterpret_cast<const ull*>(&s_b2t[2 * p]);
        tfa2[p] = bb; tfb2[p] = bb;
    }
    #pragma unroll
    for (int j = 0; j < HH; ++j) {
        const ulonglong2* row = reinterpret_cast<const ulonglong2*>(s_W2t[j]);
        ulonglong2 r0 = row[0], r1 = row[1], r2 = row[2], r3 = row[3];
        ull hj0 = pack2(ha[j], ha[j]);
        ull hj1 = pack2(hb[j], hb[j]);
        tfa2[0] = fma2(hj0, r0.x, tfa2[0]); tfa2[1] = fma2(hj0, r0.y, tfa2[1]);
        tfa2[2] = fma2(hj0, r1.x, tfa2[2]); tfa2[3] = fma2(hj0, r1.y, tfa2[3]);
        tfa2[4] = fma2(hj0, r2.x, tfa2[4]); tfa2[5] = fma2(hj0, r2.y, tfa2[5]);
        tfa2[6] = fma2(hj0, r3.x, tfa2[6]); tfa2[7] = fma2(hj0, r3.y, tfa2[7]);
        tfb2[0] = fma2(hj1, r0.x, tfb2[0]); tfb2[1] = fma2(hj1, r0.y, tfb2[1]);
        tfb2[2] = fma2(hj1, r1.x, tfb2[2]); tfb2[3] = fma2(hj1, r1.y, tfb2[3]);
        tfb2[4] = fma2(hj1, r2.x, tfb2[4]); tfb2[5] = fma2(hj1, r2.y, tfb2[5]);
        tfb2[6] = fma2(hj1, r3.x, tfb2[6]); tfb2[7] = fma2(hj1, r3.y, tfb2[7]);
    }

    // scalar part of output: const + tf . wv  (tpart folded analytically)
    float acc0, acc1;
    {
        ull va = pack2(0.0f, 0.0f), vb = pack2(0.0f, 0.0f);
        #pragma unroll
        for (int p = 0; p < 8; ++p) {
            ull wp = *reinterpret_cast<const ull*>(&s_wv[2 * p]);
            va = fma2(tfa2[p], wp, va);
            vb = fma2(tfb2[p], wp, vb);
        }
        float l, h;
        unpack2(va, l, h); acc0 = s_const + l + h;
        unpack2(vb, l, h); acc1 = s_const + l + h;
    }

    // pre-scaled -2*tf
    ull ma[8], mb[8];
    {
        ull n2 = pack2(-2.0f, -2.0f);
        #pragma unroll
        for (int p = 0; p < 8; ++p) { ma[p] = mul2(tfa2[p], n2); mb[p] = mul2(tfb2[p], n2); }
    }

    // ---- kNN for both tracks, branch-free top-8 ----
    unsigned int Aa[KK], Ab[KK];
    #pragma unroll
    for (int k = 0; k < KK; ++k) { Aa[k] = 0xFFFFFFFFu; Ab[k] = 0xFFFFFFFFu; }

    #pragma unroll 2
    for (int s = 0; s < NSV; ++s) {
        const ulonglong2* r = reinterpret_cast<const ulonglong2*>(s_sv[s]);
        ulonglong2 q0 = r[0], q1 = r[1], q2 = r[2], q3 = r[3];
        ull initv = pack2(s_ssq[s], 0.0f);
        ull aA = fma2(ma[0], q0.x, initv);
        ull aB = fma2(mb[0], q0.x, initv);
        aA = fma2(ma[1], q0.y, aA);  aB = fma2(mb[1], q0.y, aB);
        aA = fma2(ma[2], q1.x, aA);  aB = fma2(mb[2], q1.x, aB);
        aA = fma2(ma[3], q1.y, aA);  aB = fma2(mb[3], q1.y, aB);
        aA = fma2(ma[4], q2.x, aA);  aB = fma2(mb[4], q2.x, aB);
        aA = fma2(ma[5], q2.y, aA);  aB = fma2(mb[5], q2.y, aB);
        aA = fma2(ma[6], q3.x, aA);  aB = fma2(mb[6], q3.x, aB);
        aA = fma2(ma[7], q3.y, aA);  aB = fma2(mb[7], q3.y, aB);
        float lA, hA, lB, hB;
        unpack2(aA, lA, hA);
        unpack2(aB, lB, hB);
        unsigned int uA = __float_as_uint(lA + hA);
        unsigned int uB = __float_as_uint(lB + hB);
        uA ^= (unsigned int)(((int)uA >> 31)) | 0x80000000u;
        uB ^= (unsigned int)(((int)uB >> 31)) | 0x80000000u;
        unsigned int tA = (uA & 0xFFFFFF80u) | (unsigned int)s;
        unsigned int tB = (uB & 0xFFFFFF80u) | (unsigned int)s;
        #pragma unroll
        for (int j = 0; j < KK; ++j) {
            unsigned int la = min(Aa[j], tA); tA = max(Aa[j], tA); Aa[j] = la;
            unsigned int lb = min(Ab[j], tB); tB = max(Ab[j], tB); Ab[j] = lb;
        }
    }

    // ---- max-pool over neighbor projections + output, per track ----
    float osum = 0.0f;
    #pragma unroll
    for (int trk = 0; trk < 2; ++trk) {
        const unsigned int* A = trk ? Ab : Aa;
        float acc = trk ? acc1 : acc0;
        float pm[HH];
        #pragma unroll
        for (int h = 0; h < HH; ++h) pm[h] = __int_as_float(0xff800000);
        #pragma unroll
        for (int k = 0; k < KK; ++k) {
            int idx = (int)(A[k] & 0x7Fu);
            const float4* pr = reinterpret_cast<const float4*>(s_proj[idx]);
            const float4 p0 = pr[0], p1 = pr[1], p2 = pr[2], p3 = pr[3];
            pm[0]  = fmaxf(pm[0],  p0.x); pm[1]  = fmaxf(pm[1],  p0.y);
            pm[2]  = fmaxf(pm[2],  p0.z); pm[3]  = fmaxf(pm[3],  p0.w);
            pm[4]  = fmaxf(pm[4],  p1.x); pm[5]  = fmaxf(pm[5],  p1.y);
            pm[6]  = fmaxf(pm[6],  p1.z); pm[7]  = fmaxf(pm[7],  p1.w);
            pm[8]  = fmaxf(pm[8],  p2.x); pm[9]  = fmaxf(pm[9],  p2.y);
            pm[10] = fmaxf(pm[10], p2.z); pm[11] = fmaxf(pm[11], p2.w);
            pm[12] = fmaxf(pm[12], p3.x); pm[13] = fmaxf(pm[13], p3.y);
            pm[14] = fmaxf(pm[14], p3.z); pm[15] = fmaxf(pm[15], p3.w);
        }
        #pragma unroll
        for (int h = 0; h < HH; ++h) acc = fmaf(pm[h], s_Wo[h], acc);
        osum += 1.0f / (1.0f + expf(-acc));
    }

    // ---- block mean over 512 tracks (256 threads, 2 each) ----
    float v = osum;
    #pragma unroll
    for (int off = 16; off > 0; off >>= 1) v += __shfl_xor_sync(0xFFFFFFFFu, v, off);
    const int warp = tid >> 5;
    const int lane = tid & 31;
    if (lane == 0) s_warpsum[warp] = v;
    __syncthreads();
    if (tid == 0) {
        float ssum = 0.0f;
        #pragma unroll
        for (int w = 0; w < 8; ++w) ssum += s_warpsum[w];
        out[b] = ssum * (1.0f / (float)NTRK);
        if (BB + b < out_size) out[BB + b] = (float)b;
    }
}

extern "C" void kernel_launch(void* const* d_in, const int* in_sizes, int n_in,
                              void* d_out, int out_size) {
    const float* x_sv = (const float*)d_in[0];
    const float* x_trk = (const float*)d_in[1];
    // d_in[2] = batch_sv, d_in[3] = batch_trk : deterministic repeats, unused
    const float* W1s = (const float*)d_in[4];
    const float* b1s = (const float*)d_in[5];
    const float* W2s = (const float*)d_in[6];
    const float* b2s = (const float*)d_in[7];
    const float* W1t = (const float*)d_in[8];
    const float* b1t = (const float*)d_in[9];
    const float* W2t = (const float*)d_in[10];
    const float* b2t = (const float*)d_in[11];
    const float* We  = (const float*)d_in[12];
    const float* be  = (const float*)d_in[13];
    const float* Wo  = (const float*)d_in[14];
    const float* bo  = (const float*)d_in[15];
    float* out = (float*)d_out;

    fused_gnn_kernel<<<BB, TPB>>>(x_sv, x_trk,
                                  W1s, b1s, W2s, b2s,
                                  W1t, b1t, W2t, b2t,
                                  We, be, Wo, bo,
                                  out, out_size);
}

// round 5
// speedup vs baseline: 1.9973x; 1.0773x over previous
#include <cuda_runtime.h>
#include <math.h>

typedef unsigned long long ull;

#define BB 512
#define NSV 128
#define NTRK 512
#define KK 8
#define HH 16
#define TPB 256

__device__ __forceinline__ ull pack2(float lo, float hi) {
    ull r; asm("mov.b64 %0, {%1, %2};" : "=l"(r) : "f"(lo), "f"(hi)); return r;
}
__device__ __forceinline__ void unpack2(ull v, float& lo, float& hi) {
    asm("mov.b64 {%0, %1}, %2;" : "=f"(lo), "=f"(hi) : "l"(v));
}
__device__ __forceinline__ ull fma2(ull a, ull b, ull c) {
    ull d; asm("fma.rn.f32x2 %0, %1, %2, %3;" : "=l"(d) : "l"(a), "l"(b), "l"(c)); return d;
}
__device__ __forceinline__ ull mul2(ull a, ull b) {
    ull d; asm("mul.rn.f32x2 %0, %1, %2;" : "=l"(d) : "l"(a), "l"(b)); return d;
}
__device__ __forceinline__ float elu_f(float x) { return x > 0.0f ? x : expm1f(x); }

__global__ __launch_bounds__(TPB, 3)
void fused_gnn_kernel(
    const float* __restrict__ x_sv,   // (B*NSV, 2)
    const float* __restrict__ x_trk,  // (B*NTRK, 8)
    const float* __restrict__ W1s, const float* __restrict__ b1s,
    const float* __restrict__ W2s, const float* __restrict__ b2s,
    const float* __restrict__ W1t, const float* __restrict__ b1t,
    const float* __restrict__ W2t, const float* __restrict__ b2t,
    const float* __restrict__ We,  const float* __restrict__ be,
    const float* __restrict__ Wo,  const float* __restrict__ bo,
    float* __restrict__ out, int out_size)
{
    __shared__ __align__(16) float s_sv[NSV][HH];
    __shared__ float s_ssq[NSV];
    __shared__ __align__(16) float s_proj[NSV][20];
    __shared__ __align__(16) float s_h1[NSV][HH];
    __shared__ __align__(16) float s_W1t[8][HH];
    __shared__ __align__(16) float s_W2t[HH][HH];
    __shared__ __align__(16) float s_W2s[HH][HH];
    __shared__ __align__(16) float s_WeB[HH][HH];
    __shared__ __align__(16) float s_b1t[HH], s_b2t[HH], s_wv[HH], s_Wo[HH];
    __shared__ float s_const;
    __shared__ float s_warpsum[8];

    const int b   = blockIdx.x;
    const int tid = threadIdx.x;

    // ---- stage weights ----
    for (int i = tid; i < 8 * HH; i += TPB) s_W1t[i / HH][i % HH] = W1t[i];
    for (int i = tid; i < HH * HH; i += TPB) {
        int j = i / HH, h = i % HH;
        s_W2t[j][h] = W2t[i];
        s_W2s[j][h] = W2s[i];
        s_WeB[j][h] = We[(HH + j) * HH + h];
    }
    if (tid < HH) {
        s_b1t[tid] = b1t[tid];
        s_b2t[tid] = b2t[tid];
        s_Wo[tid]  = Wo[tid];
        // wv[j] = sum_h (WeA - WeB)[j][h] * Wo[h]
        float acc = 0.0f;
        #pragma unroll
        for (int h = 0; h < HH; ++h)
            acc += (We[tid * HH + h] - We[(HH + tid) * HH + h]) * Wo[h];
        s_wv[tid] = acc;
    }
    if (tid == 0) {
        float c = bo[0];
        #pragma unroll
        for (int h = 0; h < HH; ++h) c += be[h] * Wo[h];
        s_const = c;
    }

    // ---- SV prep: 2 threads per SV, 8 columns each ----
    const int sp = tid >> 1;
    const int hc = (tid & 1) * 8;
    {
        const float x0 = x_sv[(size_t)(b * NSV + sp) * 2 + 0];
        const float x1 = x_sv[(size_t)(b * NSV + sp) * 2 + 1];
        #pragma unroll
        for (int i = 0; i < 8; ++i) {
            int h = hc + i;
            s_h1[sp][h] = elu_f(fmaf(x0, W1s[h], fmaf(x1, W1s[HH + h], b1s[h])));
        }
    }
    __syncthreads();
    {
        float a[8];
        #pragma unroll
        for (int i = 0; i < 8; ++i) a[i] = b2s[hc + i];
        #pragma unroll
        for (int j = 0; j < HH; ++j) {
            float hj = s_h1[sp][j];
            #pragma unroll
            for (int i = 0; i < 8; ++i) a[i] = fmaf(hj, s_W2s[j][hc + i], a[i]);
        }
        #pragma unroll
        for (int i = 0; i < 8; ++i) s_sv[sp][hc + i] = a[i];
    }
    __syncthreads();
    {
        float a[8];
        #pragma unroll
        for (int i = 0; i < 8; ++i) a[i] = 0.0f;
        float sq = 0.0f;
        #pragma unroll
        for (int j = 0; j < HH; ++j) {
            float fj = s_sv[sp][j];
            #pragma unroll
            for (int i = 0; i < 8; ++i) a[i] = fmaf(fj, s_WeB[j][hc + i], a[i]);
            if (hc == 0) sq = fmaf(fj, fj, sq);
        }
        #pragma unroll
        for (int i = 0; i < 8; ++i) s_proj[sp][hc + i] = a[i];
        if (hc == 0) s_ssq[sp] = sq;
    }
    __syncthreads();

    // ---- 2 tracks per thread ----
    float acc0, acc1;   // scalar logit part per track
    ull ma[8], mb[8];   // -2 * tf, packed pairs, per track
    {
        const float4* xt0 = reinterpret_cast<const float4*>(x_trk + (size_t)(b * NTRK + tid) * 8);
        const float4* xt1 = reinterpret_cast<const float4*>(x_trk + (size_t)(b * NTRK + tid + TPB) * 8);
        const float4 xa0 = xt0[0], xb0 = xt0[1];
        const float4 xa1 = xt1[0], xb1 = xt1[1];
        const float xv0[8] = {xa0.x, xa0.y, xa0.z, xa0.w, xb0.x, xb0.y, xb0.z, xb0.w};
        const float xv1[8] = {xa1.x, xa1.y, xa1.z, xa1.w, xb1.x, xb1.y, xb1.z, xb1.w};

        ull h1a2[8], h1b2[8];
        #pragma unroll
        for (int p = 0; p < 8; ++p) {
            ull bb = *reinterpret_cast<const ull*>(&s_b1t[2 * p]);
            h1a2[p] = bb; h1b2[p] = bb;
        }
        #pragma unroll
        for (int j = 0; j < 8; ++j) {
            const ulonglong2* row = reinterpret_cast<const ulonglong2*>(s_W1t[j]);
            ulonglong2 r0 = row[0], r1 = row[1], r2 = row[2], r3 = row[3];
            ull xj0 = pack2(xv0[j], xv0[j]);
            ull xj1 = pack2(xv1[j], xv1[j]);
            h1a2[0] = fma2(xj0, r0.x, h1a2[0]); h1a2[1] = fma2(xj0, r0.y, h1a2[1]);
            h1a2[2] = fma2(xj0, r1.x, h1a2[2]); h1a2[3] = fma2(xj0, r1.y, h1a2[3]);
            h1a2[4] = fma2(xj0, r2.x, h1a2[4]); h1a2[5] = fma2(xj0, r2.y, h1a2[5]);
            h1a2[6] = fma2(xj0, r3.x, h1a2[6]); h1a2[7] = fma2(xj0, r3.y, h1a2[7]);
            h1b2[0] = fma2(xj1, r0.x, h1b2[0]); h1b2[1] = fma2(xj1, r0.y, h1b2[1]);
            h1b2[2] = fma2(xj1, r1.x, h1b2[2]); h1b2[3] = fma2(xj1, r1.y, h1b2[3]);
            h1b2[4] = fma2(xj1, r2.x, h1b2[4]); h1b2[5] = fma2(xj1, r2.y, h1b2[5]);
            h1b2[6] = fma2(xj1, r3.x, h1b2[6]); h1b2[7] = fma2(xj1, r3.y, h1b2[7]);
        }
        float ha[HH], hb[HH];
        #pragma unroll
        for (int p = 0; p < 8; ++p) {
            unpack2(h1a2[p], ha[2 * p], ha[2 * p + 1]);
            unpack2(h1b2[p], hb[2 * p], hb[2 * p + 1]);
        }
        #pragma unroll
        for (int h = 0; h < HH; ++h) { ha[h] = elu_f(ha[h]); hb[h] = elu_f(hb[h]); }

        // tf = h1 @ W2t + b2t for both tracks (reuse h1 pack registers)
        ull tfa2[8], tfb2[8];
        #pragma unroll
        for (int p = 0; p < 8; ++p) {
            ull bb = *reinterpret_cast<const ull*>(&s_b2t[2 * p]);
            tfa2[p] = bb; tfb2[p] = bb;
        }
        #pragma unroll
        for (int j = 0; j < HH; ++j) {
            const ulonglong2* row = reinterpret_cast<const ulonglong2*>(s_W2t[j]);
            ulonglong2 r0 = row[0], r1 = row[1], r2 = row[2], r3 = row[3];
            ull hj0 = pack2(ha[j], ha[j]);
            ull hj1 = pack2(hb[j], hb[j]);
            tfa2[0] = fma2(hj0, r0.x, tfa2[0]); tfa2[1] = fma2(hj0, r0.y, tfa2[1]);
            tfa2[2] = fma2(hj0, r1.x, tfa2[2]); tfa2[3] = fma2(hj0, r1.y, tfa2[3]);
            tfa2[4] = fma2(hj0, r2.x, tfa2[4]); tfa2[5] = fma2(hj0, r2.y, tfa2[5]);
            tfa2[6] = fma2(hj0, r3.x, tfa2[6]); tfa2[7] = fma2(hj0, r3.y, tfa2[7]);
            tfb2[0] = fma2(hj1, r0.x, tfb2[0]); tfb2[1] = fma2(hj1, r0.y, tfb2[1]);
            tfb2[2] = fma2(hj1, r1.x, tfb2[2]); tfb2[3] = fma2(hj1, r1.y, tfb2[3]);
            tfb2[4] = fma2(hj1, r2.x, tfb2[4]); tfb2[5] = fma2(hj1, r2.y, tfb2[5]);
            tfb2[6] = fma2(hj1, r3.x, tfb2[6]); tfb2[7] = fma2(hj1, r3.y, tfb2[7]);
        }

        // scalar logit part: const + tf . wv
        ull va = pack2(0.0f, 0.0f), vb = pack2(0.0f, 0.0f);
        #pragma unroll
        for (int p = 0; p < 8; ++p) {
            ull wp = *reinterpret_cast<const ull*>(&s_wv[2 * p]);
            va = fma2(tfa2[p], wp, va);
            vb = fma2(tfb2[p], wp, vb);
        }
        float l, h;
        unpack2(va, l, h); acc0 = s_const + l + h;
        unpack2(vb, l, h); acc1 = s_const + l + h;

        ull n2 = pack2(-2.0f, -2.0f);
        #pragma unroll
        for (int p = 0; p < 8; ++p) { ma[p] = mul2(tfa2[p], n2); mb[p] = mul2(tfb2[p], n2); }
    }

    // ---- kNN: float keys w/ index in low mantissa, FMNMX top-8 network ----
    float Aa[KK], Ab[KK];
    #pragma unroll
    for (int k = 0; k < KK; ++k) {
        Aa[k] = __int_as_float(0x7f800000);
        Ab[k] = __int_as_float(0x7f800000);
    }

    #pragma unroll 2
    for (int s = 0; s < NSV; ++s) {
        const ulonglong2* r = reinterpret_cast<const ulonglong2*>(s_sv[s]);
        ulonglong2 q0 = r[0], q1 = r[1], q2 = r[2], q3 = r[3];
        ull initv = pack2(s_ssq[s], 0.0f);
        ull aA = fma2(ma[0], q0.x, initv);
        ull aB = fma2(mb[0], q0.x, initv);
        aA = fma2(ma[1], q0.y, aA);  aB = fma2(mb[1], q0.y, aB);
        aA = fma2(ma[2], q1.x, aA);  aB = fma2(mb[2], q1.x, aB);
        aA = fma2(ma[3], q1.y, aA);  aB = fma2(mb[3], q1.y, aB);
        aA = fma2(ma[4], q2.x, aA);  aB = fma2(mb[4], q2.x, aB);
        aA = fma2(ma[5], q2.y, aA);  aB = fma2(mb[5], q2.y, aB);
        aA = fma2(ma[6], q3.x, aA);  aB = fma2(mb[6], q3.x, aB);
        aA = fma2(ma[7], q3.y, aA);  aB = fma2(mb[7], q3.y, aB);
        float lA, hA, lB, hB;
        unpack2(aA, lA, hA);
        unpack2(aB, lB, hB);
        // pack sv index into low 7 mantissa bits (single LOP3), compare as floats
        float tA = __uint_as_float((__float_as_uint(lA + hA) & 0xFFFFFF80u) | (unsigned)s);
        float tB = __uint_as_float((__float_as_uint(lB + hB) & 0xFFFFFF80u) | (unsigned)s);
        #pragma unroll
        for (int j = 0; j < KK; ++j) {
            float la = fminf(Aa[j], tA); tA = fmaxf(Aa[j], tA); Aa[j] = la;
            float lb = fminf(Ab[j], tB); tB = fmaxf(Ab[j], tB); Ab[j] = lb;
        }
    }

    // ---- max-pool over neighbor projections + output, per track ----
    float osum = 0.0f;
    #pragma unroll
    for (int trk = 0; trk < 2; ++trk) {
        const float* A = trk ? Ab : Aa;
        float acc = trk ? acc1 : acc0;
        float pm[HH];
        #pragma unroll
        for (int h = 0; h < HH; ++h) pm[h] = __int_as_float(0xff800000);
        #pragma unroll
        for (int k = 0; k < KK; ++k) {
            int idx = (int)(__float_as_uint(A[k]) & 0x7Fu);
            const float4* pr = reinterpret_cast<const float4*>(s_proj[idx]);
            const float4 p0 = pr[0], p1 = pr[1], p2 = pr[2], p3 = pr[3];
            pm[0]  = fmaxf(pm[0],  p0.x); pm[1]  = fmaxf(pm[1],  p0.y);
            pm[2]  = fmaxf(pm[2],  p0.z); pm[3]  = fmaxf(pm[3],  p0.w);
            pm[4]  = fmaxf(pm[4],  p1.x); pm[5]  = fmaxf(pm[5],  p1.y);
            pm[6]  = fmaxf(pm[6],  p1.z); pm[7]  = fmaxf(pm[7],  p1.w);
            pm[8]  = fmaxf(pm[8],  p2.x); pm[9]  = fmaxf(pm[9],  p2.y);
            pm[10] = fmaxf(pm[10], p2.z); pm[11] = fmaxf(pm[11], p2.w);
            pm[12] = fmaxf(pm[12], p3.x); pm[13] = fmaxf(pm[13], p3.y);
            pm[14] = fmaxf(pm[14], p3.z); pm[15] = fmaxf(pm[15], p3.w);
        }
        #pragma unroll
        for (int h = 0; h < HH; ++h) acc = fmaf(pm[h], s_Wo[h], acc);
        osum += 1.0f / (1.0f + expf(-acc));
    }

    // ---- block mean over 512 tracks ----
    float v = osum;
    #pragma unroll
    for (int off = 16; off > 0; off >>= 1) v += __shfl_xor_sync(0xFFFFFFFFu, v, off);
    const int warp = tid >> 5;
    const int lane = tid & 31;
    if (lane == 0) s_warpsum[warp] = v;
    __syncthreads();
    if (tid == 0) {
        float ssum = 0.0f;
        #pragma unroll
        for (int w = 0; w < 8; ++w) ssum += s_warpsum[w];
        out[b] = ssum * (1.0f / (float)NTRK);
        if (BB + b < out_size) out[BB + b] = (float)b;
    }
}

extern "C" void kernel_launch(void* const* d_in, const int* in_sizes, int n_in,
                              void* d_out, int out_size) {
    const float* x_sv = (const float*)d_in[0];
    const float* x_trk = (const float*)d_in[1];
    // d_in[2] = batch_sv, d_in[3] = batch_trk : deterministic repeats, unused
    const float* W1s = (const float*)d_in[4];
    const float* b1s = (const float*)d_in[5];
    const float* W2s = (const float*)d_in[6];
    const float* b2s = (const float*)d_in[7];
    const float* W1t = (const float*)d_in[8];
    const float* b1t = (const float*)d_in[9];
    const float* W2t = (const float*)d_in[10];
    const float* b2t = (const float*)d_in[11];
    const float* We  = (const float*)d_in[12];
    const float* be  = (const float*)d_in[13];
    const float* Wo  = (const float*)d_in[14];
    const float* bo  = (const float*)d_in[15];
    float* out = (float*)d_out;

    fused_gnn_kernel<<<BB, TPB>>>(x_sv, x_trk,
                                  W1s, b1s, W2s, b2s,
                                  W1t, b1t, W2t, b2t,
                                  We, be, Wo, bo,
                                  out, out_size);
}

// round 6
// speedup vs baseline: 2.2797x; 1.1414x over previous
#include <cuda_runtime.h>
#include <math.h>

typedef unsigned long long ull;

#define BB 512
#define NSV 128
#define NTRK 512
#define KK 8
#define HH 16
#define TPB 256

__device__ __forceinline__ ull pack2(float lo, float hi) {
    ull r; asm("mov.b64 %0, {%1, %2};" : "=l"(r) : "f"(lo), "f"(hi)); return r;
}
__device__ __forceinline__ void unpack2(ull v, float& lo, float& hi) {
    asm("mov.b64 {%0, %1}, %2;" : "=f"(lo), "=f"(hi) : "l"(v));
}
__device__ __forceinline__ ull fma2(ull a, ull b, ull c) {
    ull d; asm("fma.rn.f32x2 %0, %1, %2, %3;" : "=l"(d) : "l"(a), "l"(b), "l"(c)); return d;
}
__device__ __forceinline__ ull mul2(ull a, ull b) {
    ull d; asm("mul.rn.f32x2 %0, %1, %2;" : "=l"(d) : "l"(a), "l"(b)); return d;
}
__device__ __forceinline__ float elu_f(float x) { return x > 0.0f ? x : expm1f(x); }

#define CE(a, b) { float _lo = fminf(a, b); b = fmaxf(a, b); a = _lo; }

// Batcher odd-even mergesort, 8 elements, 19 CE, depth 6 -> ascending
__device__ __forceinline__ void sort8(float c[8]) {
    CE(c[0], c[1]); CE(c[2], c[3]); CE(c[4], c[5]); CE(c[6], c[7]);
    CE(c[0], c[2]); CE(c[1], c[3]); CE(c[4], c[6]); CE(c[5], c[7]);
    CE(c[1], c[2]); CE(c[5], c[6]);
    CE(c[0], c[4]); CE(c[1], c[5]); CE(c[2], c[6]); CE(c[3], c[7]);
    CE(c[2], c[4]); CE(c[3], c[5]);
    CE(c[1], c[2]); CE(c[3], c[4]); CE(c[5], c[6]);
}

// A (sorted asc) <- 8 smallest of A ∪ c (c sorted asc), kept sorted asc.
// min(A[i], c[7-i]) = lower half of 16-elem bitonic merge (bitonic seq), then 12-CE cleanup.
__device__ __forceinline__ void merge8(float A[8], const float c[8]) {
    #pragma unroll
    for (int i = 0; i < 8; ++i) A[i] = fminf(A[i], c[7 - i]);
    CE(A[0], A[4]); CE(A[1], A[5]); CE(A[2], A[6]); CE(A[3], A[7]);
    CE(A[0], A[2]); CE(A[1], A[3]); CE(A[4], A[6]); CE(A[5], A[7]);
    CE(A[0], A[1]); CE(A[2], A[3]); CE(A[4], A[5]); CE(A[6], A[7]);
}

__global__ __launch_bounds__(TPB, 3)
void fused_gnn_kernel(
    const float* __restrict__ x_sv,   // (B*NSV, 2)
    const float* __restrict__ x_trk,  // (B*NTRK, 8)
    const float* __restrict__ W1s, const float* __restrict__ b1s,
    const float* __restrict__ W2s, const float* __restrict__ b2s,
    const float* __restrict__ W1t, const float* __restrict__ b1t,
    const float* __restrict__ W2t, const float* __restrict__ b2t,
    const float* __restrict__ We,  const float* __restrict__ be,
    const float* __restrict__ Wo,  const float* __restrict__ bo,
    float* __restrict__ out, int out_size)
{
    __shared__ __align__(16) float s_sv[NSV][HH];
    __shared__ float s_ssq[NSV];
    __shared__ __align__(16) float s_proj[NSV][20];
    __shared__ __align__(16) float s_h1[NSV][HH];
    __shared__ __align__(16) float s_W1t[8][HH];
    __shared__ __align__(16) float s_W2t[HH][HH];
    __shared__ __align__(16) float s_W2s[HH][HH];
    __shared__ __align__(16) float s_WeB[HH][HH];
    __shared__ __align__(16) float s_b1t[HH], s_b2t[HH], s_wv[HH], s_Wo[HH];
    __shared__ float s_const;
    __shared__ float s_warpsum[8];

    const int b   = blockIdx.x;
    const int tid = threadIdx.x;

    // ---- stage weights ----
    for (int i = tid; i < 8 * HH; i += TPB) s_W1t[i / HH][i % HH] = W1t[i];
    for (int i = tid; i < HH * HH; i += TPB) {
        int j = i / HH, h = i % HH;
        s_W2t[j][h] = W2t[i];
        s_W2s[j][h] = W2s[i];
        s_WeB[j][h] = We[(HH + j) * HH + h];
    }
    if (tid < HH) {
        s_b1t[tid] = b1t[tid];
        s_b2t[tid] = b2t[tid];
        s_Wo[tid]  = Wo[tid];
        float acc = 0.0f;
        #pragma unroll
        for (int h = 0; h < HH; ++h)
            acc += (We[tid * HH + h] - We[(HH + tid) * HH + h]) * Wo[h];
        s_wv[tid] = acc;
    }
    if (tid == 0) {
        float c = bo[0];
        #pragma unroll
        for (int h = 0; h < HH; ++h) c += be[h] * Wo[h];
        s_const = c;
    }

    // ---- SV prep: 2 threads per SV, 8 columns each ----
    const int sp = tid >> 1;
    const int hc = (tid & 1) * 8;
    {
        const float x0 = x_sv[(size_t)(b * NSV + sp) * 2 + 0];
        const float x1 = x_sv[(size_t)(b * NSV + sp) * 2 + 1];
        #pragma unroll
        for (int i = 0; i < 8; ++i) {
            int h = hc + i;
            s_h1[sp][h] = elu_f(fmaf(x0, W1s[h], fmaf(x1, W1s[HH + h], b1s[h])));
        }
    }
    __syncthreads();
    {
        float a[8];
        #pragma unroll
        for (int i = 0; i < 8; ++i) a[i] = b2s[hc + i];
        #pragma unroll
        for (int j = 0; j < HH; ++j) {
            float hj = s_h1[sp][j];
            #pragma unroll
            for (int i = 0; i < 8; ++i) a[i] = fmaf(hj, s_W2s[j][hc + i], a[i]);
        }
        #pragma unroll
        for (int i = 0; i < 8; ++i) s_sv[sp][hc + i] = a[i];
    }
    __syncthreads();
    {
        float a[8];
        #pragma unroll
        for (int i = 0; i < 8; ++i) a[i] = 0.0f;
        float sq = 0.0f;
        #pragma unroll
        for (int j = 0; j < HH; ++j) {
            float fj = s_sv[sp][j];
            #pragma unroll
            for (int i = 0; i < 8; ++i) a[i] = fmaf(fj, s_WeB[j][hc + i], a[i]);
            if (hc == 0) sq = fmaf(fj, fj, sq);
        }
        #pragma unroll
        for (int i = 0; i < 8; ++i) s_proj[sp][hc + i] = a[i];
        if (hc == 0) s_ssq[sp] = sq;
    }
    __syncthreads();

    // ---- 2 tracks per thread: MLPs + scalar logit part ----
    float acc0, acc1;
    ull ma[8], mb[8];   // -2 * tf, packed pairs
    {
        const float4* xt0 = reinterpret_cast<const float4*>(x_trk + (size_t)(b * NTRK + tid) * 8);
        const float4* xt1 = reinterpret_cast<const float4*>(x_trk + (size_t)(b * NTRK + tid + TPB) * 8);
        const float4 xa0 = xt0[0], xb0 = xt0[1];
        const float4 xa1 = xt1[0], xb1 = xt1[1];
        const float xv0[8] = {xa0.x, xa0.y, xa0.z, xa0.w, xb0.x, xb0.y, xb0.z, xb0.w};
        const float xv1[8] = {xa1.x, xa1.y, xa1.z, xa1.w, xb1.x, xb1.y, xb1.z, xb1.w};

        ull h1a2[8], h1b2[8];
        #pragma unroll
        for (int p = 0; p < 8; ++p) {
            ull bb = *reinterpret_cast<const ull*>(&s_b1t[2 * p]);
            h1a2[p] = bb; h1b2[p] = bb;
        }
        #pragma unroll
        for (int j = 0; j < 8; ++j) {
            const ulonglong2* row = reinterpret_cast<const ulonglong2*>(s_W1t[j]);
            ulonglong2 r0 = row[0], r1 = row[1], r2 = row[2], r3 = row[3];
            ull xj0 = pack2(xv0[j], xv0[j]);
            ull xj1 = pack2(xv1[j], xv1[j]);
            h1a2[0] = fma2(xj0, r0.x, h1a2[0]); h1a2[1] = fma2(xj0, r0.y, h1a2[1]);
            h1a2[2] = fma2(xj0, r1.x, h1a2[2]); h1a2[3] = fma2(xj0, r1.y, h1a2[3]);
            h1a2[4] = fma2(xj0, r2.x, h1a2[4]); h1a2[5] = fma2(xj0, r2.y, h1a2[5]);
            h1a2[6] = fma2(xj0, r3.x, h1a2[6]); h1a2[7] = fma2(xj0, r3.y, h1a2[7]);
            h1b2[0] = fma2(xj1, r0.x, h1b2[0]); h1b2[1] = fma2(xj1, r0.y, h1b2[1]);
            h1b2[2] = fma2(xj1, r1.x, h1b2[2]); h1b2[3] = fma2(xj1, r1.y, h1b2[3]);
            h1b2[4] = fma2(xj1, r2.x, h1b2[4]); h1b2[5] = fma2(xj1, r2.y, h1b2[5]);
            h1b2[6] = fma2(xj1, r3.x, h1b2[6]); h1b2[7] = fma2(xj1, r3.y, h1b2[7]);
        }
        float ha[HH], hb[HH];
        #pragma unroll
        for (int p = 0; p < 8; ++p) {
            unpack2(h1a2[p], ha[2 * p], ha[2 * p + 1]);
            unpack2(h1b2[p], hb[2 * p], hb[2 * p + 1]);
        }
        #pragma unroll
        for (int h = 0; h < HH; ++h) { ha[h] = elu_f(ha[h]); hb[h] = elu_f(hb[h]); }

        ull tfa2[8], tfb2[8];
        #pragma unroll
        for (int p = 0; p < 8; ++p) {
            ull bb = *reinterpret_cast<const ull*>(&s_b2t[2 * p]);
            tfa2[p] = bb; tfb2[p] = bb;
        }
        #pragma unroll
        for (int j = 0; j < HH; ++j) {
            const ulonglong2* row = reinterpret_cast<const ulonglong2*>(s_W2t[j]);
            ulonglong2 r0 = row[0], r1 = row[1], r2 = row[2], r3 = row[3];
            ull hj0 = pack2(ha[j], ha[j]);
            ull hj1 = pack2(hb[j], hb[j]);
            tfa2[0] = fma2(hj0, r0.x, tfa2[0]); tfa2[1] = fma2(hj0, r0.y, tfa2[1]);
            tfa2[2] = fma2(hj0, r1.x, tfa2[2]); tfa2[3] = fma2(hj0, r1.y, tfa2[3]);
            tfa2[4] = fma2(hj0, r2.x, tfa2[4]); tfa2[5] = fma2(hj0, r2.y, tfa2[5]);
            tfa2[6] = fma2(hj0, r3.x, tfa2[6]); tfa2[7] = fma2(hj0, r3.y, tfa2[7]);
            tfb2[0] = fma2(hj1, r0.x, tfb2[0]); tfb2[1] = fma2(hj1, r0.y, tfb2[1]);
            tfb2[2] = fma2(hj1, r1.x, tfb2[2]); tfb2[3] = fma2(hj1, r1.y, tfb2[3]);
            tfb2[4] = fma2(hj1, r2.x, tfb2[4]); tfb2[5] = fma2(hj1, r2.y, tfb2[5]);
            tfb2[6] = fma2(hj1, r3.x, tfb2[6]); tfb2[7] = fma2(hj1, r3.y, tfb2[7]);
        }

        ull va = pack2(0.0f, 0.0f), vb = pack2(0.0f, 0.0f);
        #pragma unroll
        for (int p = 0; p < 8; ++p) {
            ull wp = *reinterpret_cast<const ull*>(&s_wv[2 * p]);
            va = fma2(tfa2[p], wp, va);
            vb = fma2(tfb2[p], wp, vb);
        }
        float l, h;
        unpack2(va, l, h); acc0 = s_const + l + h;
        unpack2(vb, l, h); acc1 = s_const + l + h;

        ull n2 = pack2(-2.0f, -2.0f);
        #pragma unroll
        for (int p = 0; p < 8; ++p) { ma[p] = mul2(tfa2[p], n2); mb[p] = mul2(tfb2[p], n2); }
    }

    // ---- kNN: batched top-8 via sort8 + bitonic merge ----
    float Aa[KK], Ab[KK];
    #pragma unroll
    for (int k = 0; k < KK; ++k) {
        Aa[k] = __int_as_float(0x7f800000);
        Ab[k] = __int_as_float(0x7f800000);
    }

    for (int g = 0; g < NSV; g += 8) {
        float cA[8], cB[8];
        #pragma unroll
        for (int i = 0; i < 8; ++i) {
            const int s = g + i;
            const ulonglong2* r = reinterpret_cast<const ulonglong2*>(s_sv[s]);
            ulonglong2 q0 = r[0], q1 = r[1], q2 = r[2], q3 = r[3];
            ull initv = pack2(s_ssq[s], 0.0f);
            ull aA = fma2(ma[0], q0.x, initv);
            ull aB = fma2(mb[0], q0.x, initv);
            aA = fma2(ma[1], q0.y, aA);  aB = fma2(mb[1], q0.y, aB);
            aA = fma2(ma[2], q1.x, aA);  aB = fma2(mb[2], q1.x, aB);
            aA = fma2(ma[3], q1.y, aA);  aB = fma2(mb[3], q1.y, aB);
            aA = fma2(ma[4], q2.x, aA);  aB = fma2(mb[4], q2.x, aB);
            aA = fma2(ma[5], q2.y, aA);  aB = fma2(mb[5], q2.y, aB);
            aA = fma2(ma[6], q3.x, aA);  aB = fma2(mb[6], q3.x, aB);
            aA = fma2(ma[7], q3.y, aA);  aB = fma2(mb[7], q3.y, aB);
            float lA, hA, lB, hB;
            unpack2(aA, lA, hA);
            unpack2(aB, lB, hB);
            cA[i] = __uint_as_float((__float_as_uint(lA + hA) & 0xFFFFFF80u) | (unsigned)s);
            cB[i] = __uint_as_float((__float_as_uint(lB + hB) & 0xFFFFFF80u) | (unsigned)s);
        }
        sort8(cA); sort8(cB);
        merge8(Aa, cA); merge8(Ab, cB);
    }

    // ---- max-pool over neighbor projections + output ----
    float osum = 0.0f;
    #pragma unroll
    for (int trk = 0; trk < 2; ++trk) {
        const float* A = trk ? Ab : Aa;
        float acc = trk ? acc1 : acc0;
        float pm[HH];
        #pragma unroll
        for (int h = 0; h < HH; ++h) pm[h] = __int_as_float(0xff800000);
        #pragma unroll
        for (int k = 0; k < KK; ++k) {
            int idx = (int)(__float_as_uint(A[k]) & 0x7Fu);
            const float4* pr = reinterpret_cast<const float4*>(s_proj[idx]);
            const float4 p0 = pr[0], p1 = pr[1], p2 = pr[2], p3 = pr[3];
            pm[0]  = fmaxf(pm[0],  p0.x); pm[1]  = fmaxf(pm[1],  p0.y);
            pm[2]  = fmaxf(pm[2],  p0.z); pm[3]  = fmaxf(pm[3],  p0.w);
            pm[4]  = fmaxf(pm[4],  p1.x); pm[5]  = fmaxf(pm[5],  p1.y);
            pm[6]  = fmaxf(pm[6],  p1.z); pm[7]  = fmaxf(pm[7],  p1.w);
            pm[8]  = fmaxf(pm[8],  p2.x); pm[9]  = fmaxf(pm[9],  p2.y);
            pm[10] = fmaxf(pm[10], p2.z); pm[11] = fmaxf(pm[11], p2.w);
            pm[12] = fmaxf(pm[12], p3.x); pm[13] = fmaxf(pm[13], p3.y);
            pm[14] = fmaxf(pm[14], p3.z); pm[15] = fmaxf(pm[15], p3.w);
        }
        #pragma unroll
        for (int h = 0; h < HH; ++h) acc = fmaf(pm[h], s_Wo[h], acc);
        osum += 1.0f / (1.0f + expf(-acc));
    }

    // ---- block mean over 512 tracks ----
    float v = osum;
    #pragma unroll
    for (int off = 16; off > 0; off >>= 1) v += __shfl_xor_sync(0xFFFFFFFFu, v, off);
    const int warp = tid >> 5;
    const int lane = tid & 31;
    if (lane == 0) s_warpsum[warp] = v;
    __syncthreads();
    if (tid == 0) {
        float ssum = 0.0f;
        #pragma unroll
        for (int w = 0; w < 8; ++w) ssum += s_warpsum[w];
        out[b] = ssum * (1.0f / (float)NTRK);
        if (BB + b < out_size) out[BB + b] = (float)b;
    }
}

extern "C" void kernel_launch(void* const* d_in, const int* in_sizes, int n_in,
                              void* d_out, int out_size) {
    const float* x_sv = (const float*)d_in[0];
    const float* x_trk = (const float*)d_in[1];
    // d_in[2] = batch_sv, d_in[3] = batch_trk : deterministic repeats, unused
    const float* W1s = (const float*)d_in[4];
    const float* b1s = (const float*)d_in[5];
    const float* W2s = (const float*)d_in[6];
    const float* b2s = (const float*)d_in[7];
    const float* W1t = (const float*)d_in[8];
    const float* b1t = (const float*)d_in[9];
    const float* W2t = (const float*)d_in[10];
    const float* b2t = (const float*)d_in[11];
    const float* We  = (const float*)d_in[12];
    const float* be  = (const float*)d_in[13];
    const float* Wo  = (const float*)d_in[14];
    const float* bo  = (const float*)d_in[15];
    float* out = (float*)d_out;

    fused_gnn_kernel<<<BB, TPB>>>(x_sv, x_trk,
                                  W1s, b1s, W2s, b2s,
                                  W1t, b1t, W2t, b2t,
                                  We, be, Wo, bo,
                                  out, out_size);
}

// round 7
// speedup vs baseline: 2.3766x; 1.0425x over previous
#include <cuda_runtime.h>
#include <math.h>

typedef unsigned long long ull;

#define BB 512
#define NSV 128
#define NTRK 512
#define KK 8
#define HH 16
#define TPB 256

__device__ __forceinline__ ull pack2(float lo, float hi) {
    ull r; asm("mov.b64 %0, {%1, %2};" : "=l"(r) : "f"(lo), "f"(hi)); return r;
}
__device__ __forceinline__ void unpack2(ull v, float& lo, float& hi) {
    asm("mov.b64 {%0, %1}, %2;" : "=f"(lo), "=f"(hi) : "l"(v));
}
__device__ __forceinline__ ull fma2(ull a, ull b, ull c) {
    ull d; asm("fma.rn.f32x2 %0, %1, %2, %3;" : "=l"(d) : "l"(a), "l"(b), "l"(c)); return d;
}
__device__ __forceinline__ ull mul2(ull a, ull b) {
    ull d; asm("mul.rn.f32x2 %0, %1, %2;" : "=l"(d) : "l"(a), "l"(b)); return d;
}
__device__ __forceinline__ float elu_f(float x) { return x > 0.0f ? x : expm1f(x); }

#define CE(a, b) { float _lo = fminf(a, b); b = fmaxf(a, b); a = _lo; }

// Batcher odd-even mergesort, 8 elements, 19 CE, depth 6 -> ascending
__device__ __forceinline__ void sort8(float c[8]) {
    CE(c[0], c[1]); CE(c[2], c[3]); CE(c[4], c[5]); CE(c[6], c[7]);
    CE(c[0], c[2]); CE(c[1], c[3]); CE(c[4], c[6]); CE(c[5], c[7]);
    CE(c[1], c[2]); CE(c[5], c[6]);
    CE(c[0], c[4]); CE(c[1], c[5]); CE(c[2], c[6]); CE(c[3], c[7]);
    CE(c[2], c[4]); CE(c[3], c[5]);
    CE(c[1], c[2]); CE(c[3], c[4]); CE(c[5], c[6]);
}

// A (sorted asc) <- 8 smallest of A ∪ c (c sorted asc), kept sorted asc.
__device__ __forceinline__ void merge8(float A[8], const float c[8]) {
    #pragma unroll
    for (int i = 0; i < 8; ++i) A[i] = fminf(A[i], c[7 - i]);
    CE(A[0], A[4]); CE(A[1], A[5]); CE(A[2], A[6]); CE(A[3], A[7]);
    CE(A[0], A[2]); CE(A[1], A[3]); CE(A[4], A[6]); CE(A[5], A[7]);
    CE(A[0], A[1]); CE(A[2], A[3]); CE(A[4], A[5]); CE(A[6], A[7]);
}

__global__ __launch_bounds__(TPB, 2)
void fused_gnn_kernel(
    const float* __restrict__ x_sv,   // (B*NSV, 2)
    const float* __restrict__ x_trk,  // (B*NTRK, 8)
    const float* __restrict__ W1s, const float* __restrict__ b1s,
    const float* __restrict__ W2s, const float* __restrict__ b2s,
    const float* __restrict__ W1t, const float* __restrict__ b1t,
    const float* __restrict__ W2t, const float* __restrict__ b2t,
    const float* __restrict__ We,  const float* __restrict__ be,
    const float* __restrict__ Wo,  const float* __restrict__ bo,
    float* __restrict__ out, int out_size)
{
    // row = 16 features + (ssq, 0) pair at cols 16-17; stride 20 keeps 16B alignment
    __shared__ __align__(16) float s_sv[NSV][20];
    __shared__ __align__(16) float s_proj[NSV][20];
    __shared__ __align__(16) float s_h1[NSV][HH];
    __shared__ __align__(16) float s_W1t[8][HH];
    __shared__ __align__(16) float s_W2t[HH][HH];
    __shared__ __align__(16) float s_W2s[HH][HH];
    __shared__ __align__(16) float s_WeB[HH][HH];
    __shared__ __align__(16) float s_b1t[HH], s_b2t[HH], s_wv[HH], s_Wo[HH];
    __shared__ float s_const;
    __shared__ float s_warpsum[8];

    const int b   = blockIdx.x;
    const int tid = threadIdx.x;

    // ---- stage weights ----
    for (int i = tid; i < 8 * HH; i += TPB) s_W1t[i / HH][i % HH] = W1t[i];
    for (int i = tid; i < HH * HH; i += TPB) {
        int j = i / HH, h = i % HH;
        s_W2t[j][h] = W2t[i];
        s_W2s[j][h] = W2s[i];
        s_WeB[j][h] = We[(HH + j) * HH + h];
    }
    if (tid < HH) {
        s_b1t[tid] = b1t[tid];
        s_b2t[tid] = b2t[tid];
        s_Wo[tid]  = Wo[tid];
        float acc = 0.0f;
        #pragma unroll
        for (int h = 0; h < HH; ++h)
            acc += (We[tid * HH + h] - We[(HH + tid) * HH + h]) * Wo[h];
        s_wv[tid] = acc;
    }
    if (tid == 0) {
        float c = bo[0];
        #pragma unroll
        for (int h = 0; h < HH; ++h) c += be[h] * Wo[h];
        s_const = c;
    }

    // ---- SV prep: 2 threads per SV, 8 columns each ----
    const int sp = tid >> 1;
    const int hc = (tid & 1) * 8;
    {
        const float x0 = x_sv[(size_t)(b * NSV + sp) * 2 + 0];
        const float x1 = x_sv[(size_t)(b * NSV + sp) * 2 + 1];
        #pragma unroll
        for (int i = 0; i < 8; ++i) {
            int h = hc + i;
            s_h1[sp][h] = elu_f(fmaf(x0, W1s[h], fmaf(x1, W1s[HH + h], b1s[h])));
        }
    }
    __syncthreads();
    {
        float a[8];
        #pragma unroll
        for (int i = 0; i < 8; ++i) a[i] = b2s[hc + i];
        #pragma unroll
        for (int j = 0; j < HH; ++j) {
            float hj = s_h1[sp][j];
            #pragma unroll
            for (int i = 0; i < 8; ++i) a[i] = fmaf(hj, s_W2s[j][hc + i], a[i]);
        }
        #pragma unroll
        for (int i = 0; i < 8; ++i) s_sv[sp][hc + i] = a[i];
    }
    __syncthreads();
    {
        float a[8];
        #pragma unroll
        for (int i = 0; i < 8; ++i) a[i] = 0.0f;
        float sq = 0.0f;
        #pragma unroll
        for (int j = 0; j < HH; ++j) {
            float fj = s_sv[sp][j];
            #pragma unroll
            for (int i = 0; i < 8; ++i) a[i] = fmaf(fj, s_WeB[j][hc + i], a[i]);
            if (hc == 0) sq = fmaf(fj, fj, sq);
        }
        #pragma unroll
        for (int i = 0; i < 8; ++i) s_proj[sp][hc + i] = a[i];
        if (hc == 0) { s_sv[sp][16] = sq; s_sv[sp][17] = 0.0f; }
    }
    __syncthreads();

    // ---- 2 tracks per thread: MLPs + scalar logit part ----
    float acc0, acc1;
    ull ma[8], mb[8];   // -2 * tf, packed pairs
    {
        const float4* xt0 = reinterpret_cast<const float4*>(x_trk + (size_t)(b * NTRK + tid) * 8);
        const float4* xt1 = reinterpret_cast<const float4*>(x_trk + (size_t)(b * NTRK + tid + TPB) * 8);
        const float4 xa0 = xt0[0], xb0 = xt0[1];
        const float4 xa1 = xt1[0], xb1 = xt1[1];
        const float xv0[8] = {xa0.x, xa0.y, xa0.z, xa0.w, xb0.x, xb0.y, xb0.z, xb0.w};
        const float xv1[8] = {xa1.x, xa1.y, xa1.z, xa1.w, xb1.x, xb1.y, xb1.z, xb1.w};

        ull h1a2[8], h1b2[8];
        #pragma unroll
        for (int p = 0; p < 8; ++p) {
            ull bb = *reinterpret_cast<const ull*>(&s_b1t[2 * p]);
            h1a2[p] = bb; h1b2[p] = bb;
        }
        #pragma unroll
        for (int j = 0; j < 8; ++j) {
            const ulonglong2* row = reinterpret_cast<const ulonglong2*>(s_W1t[j]);
            ulonglong2 r0 = row[0], r1 = row[1], r2 = row[2], r3 = row[3];
            ull xj0 = pack2(xv0[j], xv0[j]);
            ull xj1 = pack2(xv1[j], xv1[j]);
            h1a2[0] = fma2(xj0, r0.x, h1a2[0]); h1a2[1] = fma2(xj0, r0.y, h1a2[1]);
            h1a2[2] = fma2(xj0, r1.x, h1a2[2]); h1a2[3] = fma2(xj0, r1.y, h1a2[3]);
            h1a2[4] = fma2(xj0, r2.x, h1a2[4]); h1a2[5] = fma2(xj0, r2.y, h1a2[5]);
            h1a2[6] = fma2(xj0, r3.x, h1a2[6]); h1a2[7] = fma2(xj0, r3.y, h1a2[7]);
            h1b2[0] = fma2(xj1, r0.x, h1b2[0]); h1b2[1] = fma2(xj1, r0.y, h1b2[1]);
            h1b2[2] = fma2(xj1, r1.x, h1b2[2]); h1b2[3] = fma2(xj1, r1.y, h1b2[3]);
            h1b2[4] = fma2(xj1, r2.x, h1b2[4]); h1b2[5] = fma2(xj1, r2.y, h1b2[5]);
            h1b2[6] = fma2(xj1, r3.x, h1b2[6]); h1b2[7] = fma2(xj1, r3.y, h1b2[7]);
        }
        float ha[HH], hb[HH];
        #pragma unroll
        for (int p = 0; p < 8; ++p) {
            unpack2(h1a2[p], ha[2 * p], ha[2 * p + 1]);
            unpack2(h1b2[p], hb[2 * p], hb[2 * p + 1]);
        }
        #pragma unroll
        for (int h = 0; h < HH; ++h) { ha[h] = elu_f(ha[h]); hb[h] = elu_f(hb[h]); }

        ull tfa2[8], tfb2[8];
        #pragma unroll
        for (int p = 0; p < 8; ++p) {
            ull bb = *reinterpret_cast<const ull*>(&s_b2t[2 * p]);
            tfa2[p] = bb; tfb2[p] = bb;
        }
        #pragma unroll
        for (int j = 0; j < HH; ++j) {
            const ulonglong2* row = reinterpret_cast<const ulonglong2*>(s_W2t[j]);
            ulonglong2 r0 = row[0], r1 = row[1], r2 = row[2], r3 = row[3];
            ull hj0 = pack2(ha[j], ha[j]);
            ull hj1 = pack2(hb[j], hb[j]);
            tfa2[0] = fma2(hj0, r0.x, tfa2[0]); tfa2[1] = fma2(hj0, r0.y, tfa2[1]);
            tfa2[2] = fma2(hj0, r1.x, tfa2[2]); tfa2[3] = fma2(hj0, r1.y, tfa2[3]);
            tfa2[4] = fma2(hj0, r2.x, tfa2[4]); tfa2[5] = fma2(hj0, r2.y, tfa2[5]);
            tfa2[6] = fma2(hj0, r3.x, tfa2[6]); tfa2[7] = fma2(hj0, r3.y, tfa2[7]);
            tfb2[0] = fma2(hj1, r0.x, tfb2[0]); tfb2[1] = fma2(hj1, r0.y, tfb2[1]);
            tfb2[2] = fma2(hj1, r1.x, tfb2[2]); tfb2[3] = fma2(hj1, r1.y, tfb2[3]);
            tfb2[4] = fma2(hj1, r2.x, tfb2[4]); tfb2[5] = fma2(hj1, r2.y, tfb2[5]);
            tfb2[6] = fma2(hj1, r3.x, tfb2[6]); tfb2[7] = fma2(hj1, r3.y, tfb2[7]);
        }

        ull va = pack2(0.0f, 0.0f), vb = pack2(0.0f, 0.0f);
        #pragma unroll
        for (int p = 0; p < 8; ++p) {
            ull wp = *reinterpret_cast<const ull*>(&s_wv[2 * p]);
            va = fma2(tfa2[p], wp, va);
            vb = fma2(tfb2[p], wp, vb);
        }
        float l, h;
        unpack2(va, l, h); acc0 = s_const + l + h;
        unpack2(vb, l, h); acc1 = s_const + l + h;

        ull n2 = pack2(-2.0f, -2.0f);
        #pragma unroll
        for (int p = 0; p < 8; ++p) { ma[p] = mul2(tfa2[p], n2); mb[p] = mul2(tfb2[p], n2); }
    }

    // ---- kNN: batch-16 top-8 (2 sorts + hierarchical bitonic merges) ----
    float Aa[KK], Ab[KK];
    #pragma unroll
    for (int k = 0; k < KK; ++k) {
        Aa[k] = __int_as_float(0x7f800000);
        Ab[k] = __int_as_float(0x7f800000);
    }

    #pragma unroll 1
    for (int g = 0; g < NSV; g += 16) {
        float cA0[8], cB0[8], cA1[8], cB1[8];
        #pragma unroll
        for (int i = 0; i < 8; ++i) {
            const int s = g + i;
            const ulonglong2* r = reinterpret_cast<const ulonglong2*>(s_sv[s]);
            ulonglong2 q0 = r[0], q1 = r[1], q2 = r[2], q3 = r[3];
            ull initv = reinterpret_cast<const ull*>(s_sv[s])[8];   // (ssq, 0)
            ull aA = fma2(ma[0], q0.x, initv);
            ull aB = fma2(mb[0], q0.x, initv);
            aA = fma2(ma[1], q0.y, aA);  aB = fma2(mb[1], q0.y, aB);
            aA = fma2(ma[2], q1.x, aA);  aB = fma2(mb[2], q1.x, aB);
            aA = fma2(ma[3], q1.y, aA);  aB = fma2(mb[3], q1.y, aB);
            aA = fma2(ma[4], q2.x, aA);  aB = fma2(mb[4], q2.x, aB);
            aA = fma2(ma[5], q2.y, aA);  aB = fma2(mb[5], q2.y, aB);
            aA = fma2(ma[6], q3.x, aA);  aB = fma2(mb[6], q3.x, aB);
            aA = fma2(ma[7], q3.y, aA);  aB = fma2(mb[7], q3.y, aB);
            float lA, hA, lB, hB;
            unpack2(aA, lA, hA);
            unpack2(aB, lB, hB);
            cA0[i] = __uint_as_float((__float_as_uint(lA + hA) & 0xFFFFFF80u) | (unsigned)s);
            cB0[i] = __uint_as_float((__float_as_uint(lB + hB) & 0xFFFFFF80u) | (unsigned)s);
        }
        #pragma unroll
        for (int i = 0; i < 8; ++i) {
            const int s = g + 8 + i;
            const ulonglong2* r = reinterpret_cast<const ulonglong2*>(s_sv[s]);
            ulonglong2 q0 = r[0], q1 = r[1], q2 = r[2], q3 = r[3];
            ull initv = reinterpret_cast<const ull*>(s_sv[s])[8];
            ull aA = fma2(ma[0], q0.x, initv);
            ull aB = fma2(mb[0], q0.x, initv);
            aA = fma2(ma[1], q0.y, aA);  aB = fma2(mb[1], q0.y, aB);
            aA = fma2(ma[2], q1.x, aA);  aB = fma2(mb[2], q1.x, aB);
            aA = fma2(ma[3], q1.y, aA);  aB = fma2(mb[3], q1.y, aB);
            aA = fma2(ma[4], q2.x, aA);  aB = fma2(mb[4], q2.x, aB);
            aA = fma2(ma[5], q2.y, aA);  aB = fma2(mb[5], q2.y, aB);
            aA = fma2(ma[6], q3.x, aA);  aB = fma2(mb[6], q3.x, aB);
            aA = fma2(ma[7], q3.y, aA);  aB = fma2(mb[7], q3.y, aB);
            float lA, hA, lB, hB;
            unpack2(aA, lA, hA);
            unpack2(aB, lB, hB);
            cA1[i] = __uint_as_float((__float_as_uint(lA + hA) & 0xFFFFFF80u) | (unsigned)s);
            cB1[i] = __uint_as_float((__float_as_uint(lB + hB) & 0xFFFFFF80u) | (unsigned)s);
        }
        sort8(cA0); sort8(cA1); sort8(cB0); sort8(cB1);
        merge8(cA0, cA1);   // cA0 <- lowest 8 of 16, sorted
        merge8(cB0, cB1);
        merge8(Aa, cA0);
        merge8(Ab, cB0);
    }

    // ---- max-pool over neighbor projections + output ----
    float osum = 0.0f;
    #pragma unroll
    for (int trk = 0; trk < 2; ++trk) {
        const float* A = trk ? Ab : Aa;
        float acc = trk ? acc1 : acc0;
        float pm[HH];
        #pragma unroll
        for (int h = 0; h < HH; ++h) pm[h] = __int_as_float(0xff800000);
        #pragma unroll
        for (int k = 0; k < KK; ++k) {
            int idx = (int)(__float_as_uint(A[k]) & 0x7Fu);
            const float4* pr = reinterpret_cast<const float4*>(s_proj[idx]);
            const float4 p0 = pr[0], p1 = pr[1], p2 = pr[2], p3 = pr[3];
            pm[0]  = fmaxf(pm[0],  p0.x); pm[1]  = fmaxf(pm[1],  p0.y);
            pm[2]  = fmaxf(pm[2],  p0.z); pm[3]  = fmaxf(pm[3],  p0.w);
            pm[4]  = fmaxf(pm[4],  p1.x); pm[5]  = fmaxf(pm[5],  p1.y);
            pm[6]  = fmaxf(pm[6],  p1.z); pm[7]  = fmaxf(pm[7],  p1.w);
            pm[8]  = fmaxf(pm[8],  p2.x); pm[9]  = fmaxf(pm[9],  p2.y);
            pm[10] = fmaxf(pm[10], p2.z); pm[11] = fmaxf(pm[11], p2.w);
            pm[12] = fmaxf(pm[12], p3.x); pm[13] = fmaxf(pm[13], p3.y);
            pm[14] = fmaxf(pm[14], p3.z); pm[15] = fmaxf(pm[15], p3.w);
        }
        #pragma unroll
        for (int h = 0; h < HH; ++h) acc = fmaf(pm[h], s_Wo[h], acc);
        osum += 1.0f / (1.0f + expf(-acc));
    }

    // ---- block mean over 512 tracks ----
    float v = osum;
    #pragma unroll
    for (int off = 16; off > 0; off >>= 1) v += __shfl_xor_sync(0xFFFFFFFFu, v, off);
    const int warp = tid >> 5;
    const int lane = tid & 31;
    if (lane == 0) s_warpsum[warp] = v;
    __syncthreads();
    if (tid == 0) {
        float ssum = 0.0f;
        #pragma unroll
        for (int w = 0; w < 8; ++w) ssum += s_warpsum[w];
        out[b] = ssum * (1.0f / (float)NTRK);
        if (BB + b < out_size) out[BB + b] = (float)b;
    }
}

extern "C" void kernel_launch(void* const* d_in, const int* in_sizes, int n_in,
                              void* d_out, int out_size) {
    const float* x_sv = (const float*)d_in[0];
    const float* x_trk = (const float*)d_in[1];
    // d_in[2] = batch_sv, d_in[3] = batch_trk : deterministic repeats, unused
    const float* W1s = (const float*)d_in[4];
    const float* b1s = (const float*)d_in[5];
    const float* W2s = (const float*)d_in[6];
    const float* b2s = (const float*)d_in[7];
    const float* W1t = (const float*)d_in[8];
    const float* b1t = (const float*)d_in[9];
    const float* W2t = (const float*)d_in[10];
    const float* b2t = (const float*)d_in[11];
    const float* We  = (const float*)d_in[12];
    const float* be  = (const float*)d_in[13];
    const float* Wo  = (const float*)d_in[14];
    const float* bo  = (const float*)d_in[15];
    float* out = (float*)d_out;

    fused_gnn_kernel<<<BB, TPB>>>(x_sv, x_trk,
                                  W1s, b1s, W2s, b2s,
                                  W1t, b1t, W2t, b2t,
                                  We, be, Wo, bo,
                                  out, out_size);
}

// round 9
// speedup vs baseline: 2.5125x; 1.0572x over previous
#include <cuda_runtime.h>
#include <math.h>

typedef unsigned long long ull;

#define BB 512
#define NSV 128
#define NTRK 512
#define KK 8
#define HH 16
#define TPB 256

__device__ __forceinline__ ull pack2(float lo, float hi) {
    ull r; asm("mov.b64 %0, {%1, %2};" : "=l"(r) : "f"(lo), "f"(hi)); return r;
}
__device__ __forceinline__ void unpack2(ull v, float& lo, float& hi) {
    asm("mov.b64 {%0, %1}, %2;" : "=f"(lo), "=f"(hi) : "l"(v));
}
__device__ __forceinline__ ull fma2(ull a, ull b, ull c) {
    ull d; asm("fma.rn.f32x2 %0, %1, %2, %3;" : "=l"(d) : "l"(a), "l"(b), "l"(c)); return d;
}
__device__ __forceinline__ ull mul2(ull a, ull b) {
    ull d; asm("mul.rn.f32x2 %0, %1, %2;" : "=l"(d) : "l"(a), "l"(b)); return d;
}
// fast ELU: |abs error| <= ~2^-21 (fine vs 1e-3 rel tolerance), ~5 instr vs ~22
__device__ __forceinline__ float elu_f(float x) { return x > 0.0f ? x : __expf(x) - 1.0f; }

#define CE(a, b) { float _lo = fminf(a, b); b = fmaxf(a, b); a = _lo; }

// Batcher odd-even mergesort, 8 elements, 19 CE, depth 6 -> ascending
__device__ __forceinline__ void sort8(float c[8]) {
    CE(c[0], c[1]); CE(c[2], c[3]); CE(c[4], c[5]); CE(c[6], c[7]);
    CE(c[0], c[2]); CE(c[1], c[3]); CE(c[4], c[6]); CE(c[5], c[7]);
    CE(c[1], c[2]); CE(c[5], c[6]);
    CE(c[0], c[4]); CE(c[1], c[5]); CE(c[2], c[6]); CE(c[3], c[7]);
    CE(c[2], c[4]); CE(c[3], c[5]);
    CE(c[1], c[2]); CE(c[3], c[4]); CE(c[5], c[6]);
}

// A (sorted asc) <- 8 smallest of A ∪ c (c sorted asc), kept sorted asc.
__device__ __forceinline__ void merge8(float A[8], const float c[8]) {
    #pragma unroll
    for (int i = 0; i < 8; ++i) A[i] = fminf(A[i], c[7 - i]);
    CE(A[0], A[4]); CE(A[1], A[5]); CE(A[2], A[6]); CE(A[3], A[7]);
    CE(A[0], A[2]); CE(A[1], A[3]); CE(A[4], A[6]); CE(A[5], A[7]);
    CE(A[0], A[1]); CE(A[2], A[3]); CE(A[4], A[5]); CE(A[6], A[7]);
}

__global__ __launch_bounds__(TPB, 2)
void fused_gnn_kernel(
    const float* __restrict__ x_sv,   // (B*NSV, 2)
    const float* __restrict__ x_trk,  // (B*NTRK, 8)
    const float* __restrict__ W1s, const float* __restrict__ b1s,
    const float* __restrict__ W2s, const float* __restrict__ b2s,
    const float* __restrict__ W1t, const float* __restrict__ b1t,
    const float* __restrict__ W2t, const float* __restrict__ b2t,
    const float* __restrict__ We,  const float* __restrict__ be,
    const float* __restrict__ Wo,  const float* __restrict__ bo,
    float* __restrict__ out, int out_size)
{
    // row = 16 features + (ssq, 0) pair at cols 16-17; stride 20 keeps 16B alignment
    __shared__ __align__(16) float s_sv[NSV][20];
    __shared__ __align__(16) float s_proj[NSV][20];
    __shared__ __align__(16) float s_h1[NSV][HH];
    __shared__ __align__(16) float s_W1t[8][HH];
    __shared__ __align__(16) float s_W2t[HH][HH];
    __shared__ __align__(16) float s_W2s[HH][HH];
    __shared__ __align__(16) float s_WeB[HH][HH];
    __shared__ __align__(16) float s_b1t[HH], s_b2t[HH], s_wv[HH], s_Wo[HH];
    __shared__ float s_const;
    __shared__ float s_warpsum[8];

    const int b   = blockIdx.x;
    const int tid = threadIdx.x;

    // ---- stage weights ----
    for (int i = tid; i < 8 * HH; i += TPB) s_W1t[i / HH][i % HH] = W1t[i];
    for (int i = tid; i < HH * HH; i += TPB) {
        int j = i / HH, h = i % HH;
        s_W2t[j][h] = W2t[i];
        s_W2s[j][h] = W2s[i];
        s_WeB[j][h] = We[(HH + j) * HH + h];
    }
    if (tid < HH) {
        s_b1t[tid] = b1t[tid];
        s_b2t[tid] = b2t[tid];
        s_Wo[tid]  = Wo[tid];
        float acc = 0.0f;
        #pragma unroll
        for (int h = 0; h < HH; ++h)
            acc += (We[tid * HH + h] - We[(HH + tid) * HH + h]) * Wo[h];
        s_wv[tid] = acc;
    }
    if (tid == 0) {
        float c = bo[0];
        #pragma unroll
        for (int h = 0; h < HH; ++h) c += be[h] * Wo[h];
        s_const = c;
    }

    // ---- SV prep: 2 threads per SV, 8 columns each ----
    const int sp = tid >> 1;
    const int hc = (tid & 1) * 8;
    {
        const float x0 = x_sv[(size_t)(b * NSV + sp) * 2 + 0];
        const float x1 = x_sv[(size_t)(b * NSV + sp) * 2 + 1];
        #pragma unroll
        for (int i = 0; i < 8; ++i) {
            int h = hc + i;
            s_h1[sp][h] = elu_f(fmaf(x0, W1s[h], fmaf(x1, W1s[HH + h], b1s[h])));
        }
    }
    __syncthreads();
    {
        float a[8];
        #pragma unroll
        for (int i = 0; i < 8; ++i) a[i] = b2s[hc + i];
        #pragma unroll
        for (int j = 0; j < HH; ++j) {
            float hj = s_h1[sp][j];
            #pragma unroll
            for (int i = 0; i < 8; ++i) a[i] = fmaf(hj, s_W2s[j][hc + i], a[i]);
        }
        #pragma unroll
        for (int i = 0; i < 8; ++i) s_sv[sp][hc + i] = a[i];
    }
    __syncthreads();
    {
        float a[8];
        #pragma unroll
        for (int i = 0; i < 8; ++i) a[i] = 0.0f;
        float sq = 0.0f;
        #pragma unroll
        for (int j = 0; j < HH; ++j) {
            float fj = s_sv[sp][j];
            #pragma unroll
            for (int i = 0; i < 8; ++i) a[i] = fmaf(fj, s_WeB[j][hc + i], a[i]);
            if (hc == 0) sq = fmaf(fj, fj, sq);
        }
        #pragma unroll
        for (int i = 0; i < 8; ++i) s_proj[sp][hc + i] = a[i];
        if (hc == 0) { s_sv[sp][16] = sq; s_sv[sp][17] = 0.0f; }
    }
    __syncthreads();

    // ---- 2 tracks per thread: MLPs + scalar logit part ----
    float acc0, acc1;
    ull ma[8], mb[8];   // -2 * tf, packed pairs
    {
        const float4* xt0 = reinterpret_cast<const float4*>(x_trk + (size_t)(b * NTRK + tid) * 8);
        const float4* xt1 = reinterpret_cast<const float4*>(x_trk + (size_t)(b * NTRK + tid + TPB) * 8);
        const float4 xa0 = xt0[0], xb0 = xt0[1];
        const float4 xa1 = xt1[0], xb1 = xt1[1];
        const float xv0[8] = {xa0.x, xa0.y, xa0.z, xa0.w, xb0.x, xb0.y, xb0.z, xb0.w};
        const float xv1[8] = {xa1.x, xa1.y, xa1.z, xa1.w, xb1.x, xb1.y, xb1.z, xb1.w};

        ull h1a2[8], h1b2[8];
        #pragma unroll
        for (int p = 0; p < 8; ++p) {
            ull bb = *reinterpret_cast<const ull*>(&s_b1t[2 * p]);
            h1a2[p] = bb; h1b2[p] = bb;
        }
        #pragma unroll
        for (int j = 0; j < 8; ++j) {
            const ulonglong2* row = reinterpret_cast<const ulonglong2*>(s_W1t[j]);
            ulonglong2 r0 = row[0], r1 = row[1], r2 = row[2], r3 = row[3];
            ull xj0 = pack2(xv0[j], xv0[j]);
            ull xj1 = pack2(xv1[j], xv1[j]);
            h1a2[0] = fma2(xj0, r0.x, h1a2[0]); h1a2[1] = fma2(xj0, r0.y, h1a2[1]);
            h1a2[2] = fma2(xj0, r1.x, h1a2[2]); h1a2[3] = fma2(xj0, r1.y, h1a2[3]);
            h1a2[4] = fma2(xj0, r2.x, h1a2[4]); h1a2[5] = fma2(xj0, r2.y, h1a2[5]);
            h1a2[6] = fma2(xj0, r3.x, h1a2[6]); h1a2[7] = fma2(xj0, r3.y, h1a2[7]);
            h1b2[0] = fma2(xj1, r0.x, h1b2[0]); h1b2[1] = fma2(xj1, r0.y, h1b2[1]);
            h1b2[2] = fma2(xj1, r1.x, h1b2[2]); h1b2[3] = fma2(xj1, r1.y, h1b2[3]);
            h1b2[4] = fma2(xj1, r2.x, h1b2[4]); h1b2[5] = fma2(xj1, r2.y, h1b2[5]);
            h1b2[6] = fma2(xj1, r3.x, h1b2[6]); h1b2[7] = fma2(xj1, r3.y, h1b2[7]);
        }
        float ha[HH], hb[HH];
        #pragma unroll
        for (int p = 0; p < 8; ++p) {
            unpack2(h1a2[p], ha[2 * p], ha[2 * p + 1]);
            unpack2(h1b2[p], hb[2 * p], hb[2 * p + 1]);
        }
        #pragma unroll
        for (int h = 0; h < HH; ++h) { ha[h] = elu_f(ha[h]); hb[h] = elu_f(hb[h]); }

        ull tfa2[8], tfb2[8];
        #pragma unroll
        for (int p = 0; p < 8; ++p) {
            ull bb = *reinterpret_cast<const ull*>(&s_b2t[2 * p]);
            tfa2[p] = bb; tfb2[p] = bb;
        }
        #pragma unroll
        for (int j = 0; j < HH; ++j) {
            const ulonglong2* row = reinterpret_cast<const ulonglong2*>(s_W2t[j]);
            ulonglong2 r0 = row[0], r1 = row[1], r2 = row[2], r3 = row[3];
            ull hj0 = pack2(ha[j], ha[j]);
            ull hj1 = pack2(hb[j], hb[j]);
            tfa2[0] = fma2(hj0, r0.x, tfa2[0]); tfa2[1] = fma2(hj0, r0.y, tfa2[1]);
            tfa2[2] = fma2(hj0, r1.x, tfa2[2]); tfa2[3] = fma2(hj0, r1.y, tfa2[3]);
            tfa2[4] = fma2(hj0, r2.x, tfa2[4]); tfa2[5] = fma2(hj0, r2.y, tfa2[5]);
            tfa2[6] = fma2(hj0, r3.x, tfa2[6]); tfa2[7] = fma2(hj0, r3.y, tfa2[7]);
            tfb2[0] = fma2(hj1, r0.x, tfb2[0]); tfb2[1] = fma2(hj1, r0.y, tfb2[1]);
            tfb2[2] = fma2(hj1, r1.x, tfb2[2]); tfb2[3] = fma2(hj1, r1.y, tfb2[3]);
            tfb2[4] = fma2(hj1, r2.x, tfb2[4]); tfb2[5] = fma2(hj1, r2.y, tfb2[5]);
            tfb2[6] = fma2(hj1, r3.x, tfb2[6]); tfb2[7] = fma2(hj1, r3.y, tfb2[7]);
        }

        ull va = pack2(0.0f, 0.0f), vb = pack2(0.0f, 0.0f);
        #pragma unroll
        for (int p = 0; p < 8; ++p) {
            ull wp = *reinterpret_cast<const ull*>(&s_wv[2 * p]);
            va = fma2(tfa2[p], wp, va);
            vb = fma2(tfb2[p], wp, vb);
        }
        float l, h;
        unpack2(va, l, h); acc0 = s_const + l + h;
        unpack2(vb, l, h); acc1 = s_const + l + h;

        ull n2 = pack2(-2.0f, -2.0f);
        #pragma unroll
        for (int p = 0; p < 8; ++p) { ma[p] = mul2(tfa2[p], n2); mb[p] = mul2(tfb2[p], n2); }
    }

    // ---- kNN: batch-16 top-8 (2 sorts + hierarchical bitonic merges) ----
    float Aa[KK], Ab[KK];
    #pragma unroll
    for (int k = 0; k < KK; ++k) {
        Aa[k] = __int_as_float(0x7f800000);
        Ab[k] = __int_as_float(0x7f800000);
    }

    #pragma unroll 1
    for (int g = 0; g < NSV; g += 16) {
        float cA0[8], cB0[8], cA1[8], cB1[8];
        #pragma unroll
        for (int i = 0; i < 8; ++i) {
            const int s = g + i;
            const ulonglong2* r = reinterpret_cast<const ulonglong2*>(s_sv[s]);
            ulonglong2 q0 = r[0], q1 = r[1], q2 = r[2], q3 = r[3];
            ull initv = reinterpret_cast<const ull*>(s_sv[s])[8];   // (ssq, 0)
            ull aA = fma2(ma[0], q0.x, initv);
            ull aB = fma2(mb[0], q0.x, initv);
            aA = fma2(ma[1], q0.y, aA);  aB = fma2(mb[1], q0.y, aB);
            aA = fma2(ma[2], q1.x, aA);  aB = fma2(mb[2], q1.x, aB);
            aA = fma2(ma[3], q1.y, aA);  aB = fma2(mb[3], q1.y, aB);
            aA = fma2(ma[4], q2.x, aA);  aB = fma2(mb[4], q2.x, aB);
            aA = fma2(ma[5], q2.y, aA);  aB = fma2(mb[5], q2.y, aB);
            aA = fma2(ma[6], q3.x, aA);  aB = fma2(mb[6], q3.x, aB);
            aA = fma2(ma[7], q3.y, aA);  aB = fma2(mb[7], q3.y, aB);
            float lA, hA, lB, hB;
            unpack2(aA, lA, hA);
            unpack2(aB, lB, hB);
            cA0[i] = __uint_as_float((__float_as_uint(lA + hA) & 0xFFFFFF80u) | (unsigned)s);
            cB0[i] = __uint_as_float((__float_as_uint(lB + hB) & 0xFFFFFF80u) | (unsigned)s);
        }
        #pragma unroll
        for (int i = 0; i < 8; ++i) {
            const int s = g + 8 + i;
            const ulonglong2* r = reinterpret_cast<const ulonglong2*>(s_sv[s]);
            ulonglong2 q0 = r[0], q1 = r[1], q2 = r[2], q3 = r[3];
            ull initv = reinterpret_cast<const ull*>(s_sv[s])[8];
            ull aA = fma2(ma[0], q0.x, initv);
            ull aB = fma2(mb[0], q0.x, initv);
            aA = fma2(ma[1], q0.y, aA);  aB = fma2(mb[1], q0.y, aB);
            aA = fma2(ma[2], q1.x, aA);  aB = fma2(mb[2], q1.x, aB);
            aA = fma2(ma[3], q1.y, aA);  aB = fma2(mb[3], q1.y, aB);
            aA = fma2(ma[4], q2.x, aA);  aB = fma2(mb[4], q2.x, aB);
            aA = fma2(ma[5], q2.y, aA);  aB = fma2(mb[5], q2.y, aB);
            aA = fma2(ma[6], q3.x, aA);  aB = fma2(mb[6], q3.x, aB);
            aA = fma2(ma[7], q3.y, aA);  aB = fma2(mb[7], q3.y, aB);
            float lA, hA, lB, hB;
            unpack2(aA, lA, hA);
            unpack2(aB, lB, hB);
            cA1[i] = __uint_as_float((__float_as_uint(lA + hA) & 0xFFFFFF80u) | (unsigned)s);
            cB1[i] = __uint_as_float((__float_as_uint(lB + hB) & 0xFFFFFF80u) | (unsigned)s);
        }
        sort8(cA0); sort8(cA1); sort8(cB0); sort8(cB1);
        merge8(cA0, cA1);   // cA0 <- lowest 8 of 16, sorted
        merge8(cB0, cB1);
        merge8(Aa, cA0);
        merge8(Ab, cB0);
    }

    // ---- max-pool over neighbor projections + output ----
    float osum = 0.0f;
    #pragma unroll
    for (int trk = 0; trk < 2; ++trk) {
        const float* A = trk ? Ab : Aa;
        float acc = trk ? acc1 : acc0;
        float pm[HH];
        #pragma unroll
        for (int h = 0; h < HH; ++h) pm[h] = __int_as_float(0xff800000);
        #pragma unroll
        for (int k = 0; k < KK; ++k) {
            int idx = (int)(__float_as_uint(A[k]) & 0x7Fu);
            const float4* pr = reinterpret_cast<const float4*>(s_proj[idx]);
            const float4 p0 = pr[0], p1 = pr[1], p2 = pr[2], p3 = pr[3];
            pm[0]  = fmaxf(pm[0],  p0.x); pm[1]  = fmaxf(pm[1],  p0.y);
            pm[2]  = fmaxf(pm[2],  p0.z); pm[3]  = fmaxf(pm[3],  p0.w);
            pm[4]  = fmaxf(pm[4],  p1.x); pm[5]  = fmaxf(pm[5],  p1.y);
            pm[6]  = fmaxf(pm[6],  p1.z); pm[7]  = fmaxf(pm[7],  p1.w);
            pm[8]  = fmaxf(pm[8],  p2.x); pm[9]  = fmaxf(pm[9],  p2.y);
            pm[10] = fmaxf(pm[10], p2.z); pm[11] = fmaxf(pm[11], p2.w);
            pm[12] = fmaxf(pm[12], p3.x); pm[13] = fmaxf(pm[13], p3.y);
            pm[14] = fmaxf(pm[14], p3.z); pm[15] = fmaxf(pm[15], p3.w);
        }
        #pragma unroll
        for (int h = 0; h < HH; ++h) acc = fmaf(pm[h], s_Wo[h], acc);
        osum += 1.0f / (1.0f + __expf(-acc));
    }

    // ---- block mean over 512 tracks ----
    float v = osum;
    #pragma unroll
    for (int off = 16; off > 0; off >>= 1) v += __shfl_xor_sync(0xFFFFFFFFu, v, off);
    const int warp = tid >> 5;
    const int lane = tid & 31;
    if (lane == 0) s_warpsum[warp] = v;
    __syncthreads();
    if (tid == 0) {
        float ssum = 0.0f;
        #pragma unroll
        for (int w = 0; w < 8; ++w) ssum += s_warpsum[w];
        out[b] = ssum * (1.0f / (float)NTRK);
        if (BB + b < out_size) out[BB + b] = (float)b;
    }
}

extern "C" void kernel_launch(void* const* d_in, const int* in_sizes, int n_in,
                              void* d_out, int out_size) {
    const float* x_sv = (const float*)d_in[0];
    const float* x_trk = (const float*)d_in[1];
    // d_in[2] = batch_sv, d_in[3] = batch_trk : deterministic repeats, unused
    const float* W1s = (const float*)d_in[4];
    const float* b1s = (const float*)d_in[5];
    const float* W2s = (const float*)d_in[6];
    const float* b2s = (const float*)d_in[7];
    const float* W1t = (const float*)d_in[8];
    const float* b1t = (const float*)d_in[9];
    const float* W2t = (const float*)d_in[10];
    const float* b2t = (const float*)d_in[11];
    const float* We  = (const float*)d_in[12];
    const float* be  = (const float*)d_in[13];
    const float* Wo  = (const float*)d_in[14];
    const float* bo  = (const float*)d_in[15];
    float* out = (float*)d_out;

    fused_gnn_kernel<<<BB, TPB>>>(x_sv, x_trk,
                                  W1s, b1s, W2s, b2s,
                                  W1t, b1t, W2t, b2t,
                                  We, be, Wo, bo,
                                  out, out_size);
}

// round 10
// speedup vs baseline: 2.6551x; 1.0568x over previous
#include <cuda_runtime.h>
#include <math.h>

typedef unsigned long long ull;

#define BB 512
#define NSV 128
#define NTRK 512
#define KK 8
#define HH 16
#define TPB 128

__device__ __forceinline__ ull pack2(float lo, float hi) {
    ull r; asm("mov.b64 %0, {%1, %2};" : "=l"(r) : "f"(lo), "f"(hi)); return r;
}
__device__ __forceinline__ void unpack2(ull v, float& lo, float& hi) {
    asm("mov.b64 {%0, %1}, %2;" : "=f"(lo), "=f"(hi) : "l"(v));
}
__device__ __forceinline__ ull fma2(ull a, ull b, ull c) {
    ull d; asm("fma.rn.f32x2 %0, %1, %2, %3;" : "=l"(d) : "l"(a), "l"(b), "l"(c)); return d;
}
__device__ __forceinline__ ull mul2(ull a, ull b) {
    ull d; asm("mul.rn.f32x2 %0, %1, %2;" : "=l"(d) : "l"(a), "l"(b)); return d;
}
__device__ __forceinline__ float elu_f(float x) { return x > 0.0f ? x : __expf(x) - 1.0f; }

#define CE(a, b) { float _lo = fminf(a, b); b = fmaxf(a, b); a = _lo; }

__device__ __forceinline__ void sort8(float c[8]) {
    CE(c[0], c[1]); CE(c[2], c[3]); CE(c[4], c[5]); CE(c[6], c[7]);
    CE(c[0], c[2]); CE(c[1], c[3]); CE(c[4], c[6]); CE(c[5], c[7]);
    CE(c[1], c[2]); CE(c[5], c[6]);
    CE(c[0], c[4]); CE(c[1], c[5]); CE(c[2], c[6]); CE(c[3], c[7]);
    CE(c[2], c[4]); CE(c[3], c[5]);
    CE(c[1], c[2]); CE(c[3], c[4]); CE(c[5], c[6]);
}

__device__ __forceinline__ void merge8(float A[8], const float c[8]) {
    #pragma unroll
    for (int i = 0; i < 8; ++i) A[i] = fminf(A[i], c[7 - i]);
    CE(A[0], A[4]); CE(A[1], A[5]); CE(A[2], A[6]); CE(A[3], A[7]);
    CE(A[0], A[2]); CE(A[1], A[3]); CE(A[4], A[6]); CE(A[5], A[7]);
    CE(A[0], A[1]); CE(A[2], A[3]); CE(A[4], A[5]); CE(A[6], A[7]);
}

// MLP + logit-scalar + (-2*tf) for two tracks sharing weight-row loads
__device__ __forceinline__ void mlp_pair(
    const float* __restrict__ xt0, const float* __restrict__ xt1,
    const float (*W1t_)[HH], const float (*W2t_)[HH],
    const float* b1t_, const float* b2t_, const float* wv_, float cst,
    float& accA, float& accB, ull maA[8], ull maB[8])
{
    const float4* p0 = reinterpret_cast<const float4*>(xt0);
    const float4* p1 = reinterpret_cast<const float4*>(xt1);
    const float4 a0 = p0[0], a1 = p0[1], b0 = p1[0], b1 = p1[1];
    const float xv0[8] = {a0.x, a0.y, a0.z, a0.w, a1.x, a1.y, a1.z, a1.w};
    const float xv1[8] = {b0.x, b0.y, b0.z, b0.w, b1.x, b1.y, b1.z, b1.w};

    ull hA[8], hB[8];
    #pragma unroll
    for (int p = 0; p < 8; ++p) {
        ull bb = *reinterpret_cast<const ull*>(&b1t_[2 * p]);
        hA[p] = bb; hB[p] = bb;
    }
    #pragma unroll
    for (int j = 0; j < 8; ++j) {
        const ulonglong2* row = reinterpret_cast<const ulonglong2*>(W1t_[j]);
        ulonglong2 r0 = row[0], r1 = row[1], r2 = row[2], r3 = row[3];
        ull xj0 = pack2(xv0[j], xv0[j]);
        ull xj1 = pack2(xv1[j], xv1[j]);
        hA[0] = fma2(xj0, r0.x, hA[0]); hA[1] = fma2(xj0, r0.y, hA[1]);
        hA[2] = fma2(xj0, r1.x, hA[2]); hA[3] = fma2(xj0, r1.y, hA[3]);
        hA[4] = fma2(xj0, r2.x, hA[4]); hA[5] = fma2(xj0, r2.y, hA[5]);
        hA[6] = fma2(xj0, r3.x, hA[6]); hA[7] = fma2(xj0, r3.y, hA[7]);
        hB[0] = fma2(xj1, r0.x, hB[0]); hB[1] = fma2(xj1, r0.y, hB[1]);
        hB[2] = fma2(xj1, r1.x, hB[2]); hB[3] = fma2(xj1, r1.y, hB[3]);
        hB[4] = fma2(xj1, r2.x, hB[4]); hB[5] = fma2(xj1, r2.y, hB[5]);
        hB[6] = fma2(xj1, r3.x, hB[6]); hB[7] = fma2(xj1, r3.y, hB[7]);
    }
    float ea[HH], eb[HH];
    #pragma unroll
    for (int p = 0; p < 8; ++p) {
        unpack2(hA[p], ea[2 * p], ea[2 * p + 1]);
        unpack2(hB[p], eb[2 * p], eb[2 * p + 1]);
    }
    #pragma unroll
    for (int h = 0; h < HH; ++h) { ea[h] = elu_f(ea[h]); eb[h] = elu_f(eb[h]); }

    ull tA[8], tB[8];
    #pragma unroll
    for (int p = 0; p < 8; ++p) {
        ull bb = *reinterpret_cast<const ull*>(&b2t_[2 * p]);
        tA[p] = bb; tB[p] = bb;
    }
    #pragma unroll
    for (int j = 0; j < HH; ++j) {
        const ulonglong2* row = reinterpret_cast<const ulonglong2*>(W2t_[j]);
        ulonglong2 r0 = row[0], r1 = row[1], r2 = row[2], r3 = row[3];
        ull hj0 = pack2(ea[j], ea[j]);
        ull hj1 = pack2(eb[j], eb[j]);
        tA[0] = fma2(hj0, r0.x, tA[0]); tA[1] = fma2(hj0, r0.y, tA[1]);
        tA[2] = fma2(hj0, r1.x, tA[2]); tA[3] = fma2(hj0, r1.y, tA[3]);
        tA[4] = fma2(hj0, r2.x, tA[4]); tA[5] = fma2(hj0, r2.y, tA[5]);
        tA[6] = fma2(hj0, r3.x, tA[6]); tA[7] = fma2(hj0, r3.y, tA[7]);
        tB[0] = fma2(hj1, r0.x, tB[0]); tB[1] = fma2(hj1, r0.y, tB[1]);
        tB[2] = fma2(hj1, r1.x, tB[2]); tB[3] = fma2(hj1, r1.y, tB[3]);
        tB[4] = fma2(hj1, r2.x, tB[4]); tB[5] = fma2(hj1, r2.y, tB[5]);
        tB[6] = fma2(hj1, r3.x, tB[6]); tB[7] = fma2(hj1, r3.y, tB[7]);
    }

    ull va = pack2(0.0f, 0.0f), vb = pack2(0.0f, 0.0f);
    #pragma unroll
    for (int p = 0; p < 8; ++p) {
        ull wp = *reinterpret_cast<const ull*>(&wv_[2 * p]);
        va = fma2(tA[p], wp, va);
        vb = fma2(tB[p], wp, vb);
    }
    float l, h;
    unpack2(va, l, h); accA = cst + l + h;
    unpack2(vb, l, h); accB = cst + l + h;

    ull n2 = pack2(-2.0f, -2.0f);
    #pragma unroll
    for (int p = 0; p < 8; ++p) { maA[p] = mul2(tA[p], n2); maB[p] = mul2(tB[p], n2); }
}

__global__ __launch_bounds__(TPB, 3)
void fused_gnn_kernel(
    const float* __restrict__ x_sv,   // (B*NSV, 2)
    const float* __restrict__ x_trk,  // (B*NTRK, 8)
    const float* __restrict__ W1s, const float* __restrict__ b1s,
    const float* __restrict__ W2s, const float* __restrict__ b2s,
    const float* __restrict__ W1t, const float* __restrict__ b1t,
    const float* __restrict__ W2t, const float* __restrict__ b2t,
    const float* __restrict__ We,  const float* __restrict__ be,
    const float* __restrict__ Wo,  const float* __restrict__ bo,
    float* __restrict__ out, int out_size)
{
    // row = 16 features + (ssq, 0) at cols 16-17; stride 20 keeps 16B alignment
    __shared__ __align__(16) float s_sv[NSV][20];
    __shared__ __align__(16) float s_proj[NSV][20];
    __shared__ __align__(16) float s_W1t[8][HH];
    __shared__ __align__(16) float s_W2t[HH][HH];
    __shared__ __align__(16) float s_W2s[HH][HH];
    __shared__ __align__(16) float s_WeB[HH][HH];
    __shared__ __align__(16) float s_b1t[HH], s_b2t[HH], s_wv[HH], s_Wo[HH];
    __shared__ float s_const;
    __shared__ float s_warpsum[4];

    const int b   = blockIdx.x;
    const int tid = threadIdx.x;

    // ---- stage weights ----
    for (int i = tid; i < 8 * HH; i += TPB) s_W1t[i / HH][i % HH] = W1t[i];
    for (int i = tid; i < HH * HH; i += TPB) {
        int j = i / HH, h = i % HH;
        s_W2t[j][h] = W2t[i];
        s_W2s[j][h] = W2s[i];
        s_WeB[j][h] = We[(HH + j) * HH + h];
    }
    if (tid < HH) {
        s_b1t[tid] = b1t[tid];
        s_b2t[tid] = b2t[tid];
        s_Wo[tid]  = Wo[tid];
        float acc = 0.0f;
        #pragma unroll
        for (int h = 0; h < HH; ++h)
            acc += (We[tid * HH + h] - We[(HH + tid) * HH + h]) * Wo[h];
        s_wv[tid] = acc;
    }
    if (tid == 0) {
        float c = bo[0];
        #pragma unroll
        for (int h = 0; h < HH; ++h) c += be[h] * Wo[h];
        s_const = c;
    }
    __syncthreads();

    // ---- SV prep: one SV per thread, all in registers ----
    {
        const int sp = tid;
        const float x0 = x_sv[(size_t)(b * NSV + sp) * 2 + 0];
        const float x1 = x_sv[(size_t)(b * NSV + sp) * 2 + 1];
        float h1[HH];
        #pragma unroll
        for (int h = 0; h < HH; ++h)
            h1[h] = elu_f(fmaf(x0, W1s[h], fmaf(x1, W1s[HH + h], b1s[h])));
        float f[HH];
        #pragma unroll
        for (int h = 0; h < HH; ++h) f[h] = b2s[h];
        #pragma unroll
        for (int j = 0; j < HH; ++j) {
            float hj = h1[j];
            #pragma unroll
            for (int h = 0; h < HH; ++h) f[h] = fmaf(hj, s_W2s[j][h], f[h]);
        }
        float pr[HH];
        #pragma unroll
        for (int h = 0; h < HH; ++h) pr[h] = 0.0f;
        float sq = 0.0f;
        #pragma unroll
        for (int j = 0; j < HH; ++j) {
            float fj = f[j];
            #pragma unroll
            for (int h = 0; h < HH; ++h) pr[h] = fmaf(fj, s_WeB[j][h], pr[h]);
            sq = fmaf(fj, fj, sq);
            s_sv[sp][j] = fj;
        }
        #pragma unroll
        for (int h = 0; h < HH; ++h) s_proj[sp][h] = pr[h];
        s_sv[sp][16] = sq;
        s_sv[sp][17] = 0.0f;
    }

    // ---- 4 tracks per thread: MLPs in two register-friendly passes ----
    float acc0, acc1, acc2, acc3;
    ull m0[8], m1[8], m2[8], m3[8];
    {
        const float* base = x_trk + (size_t)b * NTRK * 8;
        mlp_pair(base + (size_t)tid * 8, base + (size_t)(tid + TPB) * 8,
                 s_W1t, s_W2t, s_b1t, s_b2t, s_wv, s_const, acc0, acc1, m0, m1);
        mlp_pair(base + (size_t)(tid + 2 * TPB) * 8, base + (size_t)(tid + 3 * TPB) * 8,
                 s_W1t, s_W2t, s_b1t, s_b2t, s_wv, s_const, acc2, acc3, m2, m3);
    }
    __syncthreads();

    // ---- kNN: batch-8 top-8, 4 tracks sharing each SV row load ----
    float A0[KK], A1[KK], A2[KK], A3[KK];
    #pragma unroll
    for (int k = 0; k < KK; ++k) {
        const float inf = __int_as_float(0x7f800000);
        A0[k] = inf; A1[k] = inf; A2[k] = inf; A3[k] = inf;
    }

#define KEYCHAIN(M, OUT) { \
        ull a = fma2(M[0], q0.x, initv); \
        a = fma2(M[1], q0.y, a); \
        a = fma2(M[2], q1.x, a); \
        a = fma2(M[3], q1.y, a); \
        a = fma2(M[4], q2.x, a); \
        a = fma2(M[5], q2.y, a); \
        a = fma2(M[6], q3.x, a); \
        a = fma2(M[7], q3.y, a); \
        float lo_, hi_; unpack2(a, lo_, hi_); \
        OUT = __uint_as_float((__float_as_uint(lo_ + hi_) & 0xFFFFFF80u) | (unsigned)s); }

    #pragma unroll 1
    for (int g = 0; g < NSV; g += 8) {
        float c0[8], c1[8], c2[8], c3[8];
        #pragma unroll
        for (int i = 0; i < 8; ++i) {
            const int s = g + i;
            const ulonglong2* r = reinterpret_cast<const ulonglong2*>(s_sv[s]);
            ulonglong2 q0 = r[0], q1 = r[1], q2 = r[2], q3 = r[3];
            ull initv = reinterpret_cast<const ull*>(s_sv[s])[8];   // (ssq, 0)
            KEYCHAIN(m0, c0[i]);
            KEYCHAIN(m1, c1[i]);
            KEYCHAIN(m2, c2[i]);
            KEYCHAIN(m3, c3[i]);
        }
        sort8(c0); merge8(A0, c0);
        sort8(c1); merge8(A1, c1);
        sort8(c2); merge8(A2, c2);
        sort8(c3); merge8(A3, c3);
    }
#undef KEYCHAIN

    // ---- max-pool over neighbor projections + sigmoid, 4 tracks ----
    float osum = 0.0f;
#define POOL(Aarr, accv) { \
        float pm[HH]; \
        _Pragma("unroll") \
        for (int h = 0; h < HH; ++h) pm[h] = __int_as_float(0xff800000); \
        _Pragma("unroll") \
        for (int k = 0; k < KK; ++k) { \
            int idx = (int)(__float_as_uint(Aarr[k]) & 0x7Fu); \
            const float4* pr_ = reinterpret_cast<const float4*>(s_proj[idx]); \
            const float4 p0 = pr_[0], p1 = pr_[1], p2 = pr_[2], p3 = pr_[3]; \
            pm[0]  = fmaxf(pm[0],  p0.x); pm[1]  = fmaxf(pm[1],  p0.y); \
            pm[2]  = fmaxf(pm[2],  p0.z); pm[3]  = fmaxf(pm[3],  p0.w); \
            pm[4]  = fmaxf(pm[4],  p1.x); pm[5]  = fmaxf(pm[5],  p1.y); \
            pm[6]  = fmaxf(pm[6],  p1.z); pm[7]  = fmaxf(pm[7],  p1.w); \
            pm[8]  = fmaxf(pm[8],  p2.x); pm[9]  = fmaxf(pm[9],  p2.y); \
            pm[10] = fmaxf(pm[10], p2.z); pm[11] = fmaxf(pm[11], p2.w); \
            pm[12] = fmaxf(pm[12], p3.x); pm[13] = fmaxf(pm[13], p3.y); \
            pm[14] = fmaxf(pm[14], p3.z); pm[15] = fmaxf(pm[15], p3.w); \
        } \
        float a_ = accv; \
        _Pragma("unroll") \
        for (int h = 0; h < HH; ++h) a_ = fmaf(pm[h], s_Wo[h], a_); \
        osum += 1.0f / (1.0f + __expf(-a_)); }

    POOL(A0, acc0);
    POOL(A1, acc1);
    POOL(A2, acc2);
    POOL(A3, acc3);
#undef POOL

    // ---- block mean over 512 tracks (128 threads, 4 each) ----
    float v = osum;
    #pragma unroll
    for (int off = 16; off > 0; off >>= 1) v += __shfl_xor_sync(0xFFFFFFFFu, v, off);
    const int warp = tid >> 5;
    const int lane = tid & 31;
    if (lane == 0) s_warpsum[warp] = v;
    __syncthreads();
    if (tid == 0) {
        float ssum = s_warpsum[0] + s_warpsum[1] + s_warpsum[2] + s_warpsum[3];
        out[b] = ssum * (1.0f / (float)NTRK);
        if (BB + b < out_size) out[BB + b] = (float)b;
    }
}

extern "C" void kernel_launch(void* const* d_in, const int* in_sizes, int n_in,
                              void* d_out, int out_size) {
    const float* x_sv = (const float*)d_in[0];
    const float* x_trk = (const float*)d_in[1];
    // d_in[2] = batch_sv, d_in[3] = batch_trk : deterministic repeats, unused
    const float* W1s = (const float*)d_in[4];
    const float* b1s = (const float*)d_in[5];
    const float* W2s = (const float*)d_in[6];
    const float* b2s = (const float*)d_in[7];
    const float* W1t = (const float*)d_in[8];
    const float* b1t = (const float*)d_in[9];
    const float* W2t = (const float*)d_in[10];
    const float* b2t = (const float*)d_in[11];
    const float* We  = (const float*)d_in[12];
    const float* be  = (const float*)d_in[13];
    const float* Wo  = (const float*)d_in[14];
    const float* bo  = (const float*)d_in[15];
    float* out = (float*)d_out;

    fused_gnn_kernel<<<BB, TPB>>>(x_sv, x_trk,
                                  W1s, b1s, W2s, b2s,
                                  W1t, b1t, W2t, b2t,
                                  We, be, Wo, bo,
                                  out, out_size);
}

// round 11
// speedup vs baseline: 2.7488x; 1.0353x over previous
#include <cuda_runtime.h>
#include <math.h>

typedef unsigned long long ull;

#define BB 512
#define NSV 128
#define NTRK 512
#define KK 8
#define HH 16
#define TPB 128

__device__ float g_partial[2 * BB];

__device__ __forceinline__ ull pack2(float lo, float hi) {
    ull r; asm("mov.b64 %0, {%1, %2};" : "=l"(r) : "f"(lo), "f"(hi)); return r;
}
__device__ __forceinline__ void unpack2(ull v, float& lo, float& hi) {
    asm("mov.b64 {%0, %1}, %2;" : "=f"(lo), "=f"(hi) : "l"(v));
}
__device__ __forceinline__ ull fma2(ull a, ull b, ull c) {
    ull d; asm("fma.rn.f32x2 %0, %1, %2, %3;" : "=l"(d) : "l"(a), "l"(b), "l"(c)); return d;
}
__device__ __forceinline__ ull mul2(ull a, ull b) {
    ull d; asm("mul.rn.f32x2 %0, %1, %2;" : "=l"(d) : "l"(a), "l"(b)); return d;
}
__device__ __forceinline__ float elu_f(float x) { return x > 0.0f ? x : __expf(x) - 1.0f; }

#define CE(a, b) { float _lo = fminf(a, b); b = fmaxf(a, b); a = _lo; }

__device__ __forceinline__ void sort8(float c[8]) {
    CE(c[0], c[1]); CE(c[2], c[3]); CE(c[4], c[5]); CE(c[6], c[7]);
    CE(c[0], c[2]); CE(c[1], c[3]); CE(c[4], c[6]); CE(c[5], c[7]);
    CE(c[1], c[2]); CE(c[5], c[6]);
    CE(c[0], c[4]); CE(c[1], c[5]); CE(c[2], c[6]); CE(c[3], c[7]);
    CE(c[2], c[4]); CE(c[3], c[5]);
    CE(c[1], c[2]); CE(c[3], c[4]); CE(c[5], c[6]);
}

__device__ __forceinline__ void merge8(float A[8], const float c[8]) {
    #pragma unroll
    for (int i = 0; i < 8; ++i) A[i] = fminf(A[i], c[7 - i]);
    CE(A[0], A[4]); CE(A[1], A[5]); CE(A[2], A[6]); CE(A[3], A[7]);
    CE(A[0], A[2]); CE(A[1], A[3]); CE(A[4], A[6]); CE(A[5], A[7]);
    CE(A[0], A[1]); CE(A[2], A[3]); CE(A[4], A[5]); CE(A[6], A[7]);
}

// MLP + logit-scalar + (-2*tf) for two tracks sharing weight-row loads
__device__ __forceinline__ void mlp_pair(
    const float* __restrict__ xt0, const float* __restrict__ xt1,
    const float (*W1t_)[HH], const float (*W2t_)[HH],
    const float* b1t_, const float* b2t_, const float* wv_, float cst,
    float& accA, float& accB, ull maA[8], ull maB[8])
{
    const float4* p0 = reinterpret_cast<const float4*>(xt0);
    const float4* p1 = reinterpret_cast<const float4*>(xt1);
    const float4 a0 = p0[0], a1 = p0[1], b0 = p1[0], b1 = p1[1];
    const float xv0[8] = {a0.x, a0.y, a0.z, a0.w, a1.x, a1.y, a1.z, a1.w};
    const float xv1[8] = {b0.x, b0.y, b0.z, b0.w, b1.x, b1.y, b1.z, b1.w};

    ull hA[8], hB[8];
    #pragma unroll
    for (int p = 0; p < 8; ++p) {
        ull bb = *reinterpret_cast<const ull*>(&b1t_[2 * p]);
        hA[p] = bb; hB[p] = bb;
    }
    #pragma unroll
    for (int j = 0; j < 8; ++j) {
        const ulonglong2* row = reinterpret_cast<const ulonglong2*>(W1t_[j]);
        ulonglong2 r0 = row[0], r1 = row[1], r2 = row[2], r3 = row[3];
        ull xj0 = pack2(xv0[j], xv0[j]);
        ull xj1 = pack2(xv1[j], xv1[j]);
        hA[0] = fma2(xj0, r0.x, hA[0]); hA[1] = fma2(xj0, r0.y, hA[1]);
        hA[2] = fma2(xj0, r1.x, hA[2]); hA[3] = fma2(xj0, r1.y, hA[3]);
        hA[4] = fma2(xj0, r2.x, hA[4]); hA[5] = fma2(xj0, r2.y, hA[5]);
        hA[6] = fma2(xj0, r3.x, hA[6]); hA[7] = fma2(xj0, r3.y, hA[7]);
        hB[0] = fma2(xj1, r0.x, hB[0]); hB[1] = fma2(xj1, r0.y, hB[1]);
        hB[2] = fma2(xj1, r1.x, hB[2]); hB[3] = fma2(xj1, r1.y, hB[3]);
        hB[4] = fma2(xj1, r2.x, hB[4]); hB[5] = fma2(xj1, r2.y, hB[5]);
        hB[6] = fma2(xj1, r3.x, hB[6]); hB[7] = fma2(xj1, r3.y, hB[7]);
    }
    float ea[HH], eb[HH];
    #pragma unroll
    for (int p = 0; p < 8; ++p) {
        unpack2(hA[p], ea[2 * p], ea[2 * p + 1]);
        unpack2(hB[p], eb[2 * p], eb[2 * p + 1]);
    }
    #pragma unroll
    for (int h = 0; h < HH; ++h) { ea[h] = elu_f(ea[h]); eb[h] = elu_f(eb[h]); }

    ull tA[8], tB[8];
    #pragma unroll
    for (int p = 0; p < 8; ++p) {
        ull bb = *reinterpret_cast<const ull*>(&b2t_[2 * p]);
        tA[p] = bb; tB[p] = bb;
    }
    #pragma unroll
    for (int j = 0; j < HH; ++j) {
        const ulonglong2* row = reinterpret_cast<const ulonglong2*>(W2t_[j]);
        ulonglong2 r0 = row[0], r1 = row[1], r2 = row[2], r3 = row[3];
        ull hj0 = pack2(ea[j], ea[j]);
        ull hj1 = pack2(eb[j], eb[j]);
        tA[0] = fma2(hj0, r0.x, tA[0]); tA[1] = fma2(hj0, r0.y, tA[1]);
        tA[2] = fma2(hj0, r1.x, tA[2]); tA[3] = fma2(hj0, r1.y, tA[3]);
        tA[4] = fma2(hj0, r2.x, tA[4]); tA[5] = fma2(hj0, r2.y, tA[5]);
        tA[6] = fma2(hj0, r3.x, tA[6]); tA[7] = fma2(hj0, r3.y, tA[7]);
        tB[0] = fma2(hj1, r0.x, tB[0]); tB[1] = fma2(hj1, r0.y, tB[1]);
        tB[2] = fma2(hj1, r1.x, tB[2]); tB[3] = fma2(hj1, r1.y, tB[3]);
        tB[4] = fma2(hj1, r2.x, tB[4]); tB[5] = fma2(hj1, r2.y, tB[5]);
        tB[6] = fma2(hj1, r3.x, tB[6]); tB[7] = fma2(hj1, r3.y, tB[7]);
    }

    ull va = pack2(0.0f, 0.0f), vb = pack2(0.0f, 0.0f);
    #pragma unroll
    for (int p = 0; p < 8; ++p) {
        ull wp = *reinterpret_cast<const ull*>(&wv_[2 * p]);
        va = fma2(tA[p], wp, va);
        vb = fma2(tB[p], wp, vb);
    }
    float l, h;
    unpack2(va, l, h); accA = cst + l + h;
    unpack2(vb, l, h); accB = cst + l + h;

    ull n2 = pack2(-2.0f, -2.0f);
    #pragma unroll
    for (int p = 0; p < 8; ++p) { maA[p] = mul2(tA[p], n2); maB[p] = mul2(tB[p], n2); }
}

// one CTA = one half-batch (256 tracks); partial sigmoid-sum -> g_partial
__global__ __launch_bounds__(TPB, 5)
void fused_gnn_kernel(
    const float* __restrict__ x_sv,   // (B*NSV, 2)
    const float* __restrict__ x_trk,  // (B*NTRK, 8)
    const float* __restrict__ W1s, const float* __restrict__ b1s,
    const float* __restrict__ W2s, const float* __restrict__ b2s,
    const float* __restrict__ W1t, const float* __restrict__ b1t,
    const float* __restrict__ W2t, const float* __restrict__ b2t,
    const float* __restrict__ We,  const float* __restrict__ be,
    const float* __restrict__ Wo,  const float* __restrict__ bo)
{
    __shared__ __align__(16) float s_sv[NSV][20];     // 16 feats + (ssq,0) @16
    __shared__ __align__(16) float s_proj[NSV][20];
    __shared__ __align__(16) float s_W1t[8][HH];
    __shared__ __align__(16) float s_W2t[HH][HH];
    __shared__ __align__(16) float s_W2s[HH][HH];
    __shared__ __align__(16) float s_WeB[HH][HH];
    __shared__ __align__(16) float s_b1t[HH], s_b2t[HH], s_wv[HH], s_Wo[HH];
    __shared__ float s_const;
    __shared__ float s_warpsum[4];

    const int b    = blockIdx.x >> 1;
    const int half = blockIdx.x & 1;
    const int tid  = threadIdx.x;

    // ---- stage weights ----
    for (int i = tid; i < 8 * HH; i += TPB) s_W1t[i / HH][i % HH] = W1t[i];
    for (int i = tid; i < HH * HH; i += TPB) {
        int j = i / HH, h = i % HH;
        s_W2t[j][h] = W2t[i];
        s_W2s[j][h] = W2s[i];
        s_WeB[j][h] = We[(HH + j) * HH + h];
    }
    if (tid < HH) {
        s_b1t[tid] = b1t[tid];
        s_b2t[tid] = b2t[tid];
        s_Wo[tid]  = Wo[tid];
        float acc = 0.0f;
        #pragma unroll
        for (int h = 0; h < HH; ++h)
            acc += (We[tid * HH + h] - We[(HH + tid) * HH + h]) * Wo[h];
        s_wv[tid] = acc;
    }
    if (tid == 0) {
        float c = bo[0];
        #pragma unroll
        for (int h = 0; h < HH; ++h) c += be[h] * Wo[h];
        s_const = c;
    }
    __syncthreads();

    // ---- SV prep: one SV per thread, all in registers ----
    {
        const int sp = tid;
        const float x0 = x_sv[(size_t)(b * NSV + sp) * 2 + 0];
        const float x1 = x_sv[(size_t)(b * NSV + sp) * 2 + 1];
        float h1[HH];
        #pragma unroll
        for (int h = 0; h < HH; ++h)
            h1[h] = elu_f(fmaf(x0, W1s[h], fmaf(x1, W1s[HH + h], b1s[h])));
        float f[HH];
        #pragma unroll
        for (int h = 0; h < HH; ++h) f[h] = b2s[h];
        #pragma unroll
        for (int j = 0; j < HH; ++j) {
            float hj = h1[j];
            #pragma unroll
            for (int h = 0; h < HH; ++h) f[h] = fmaf(hj, s_W2s[j][h], f[h]);
        }
        float pr[HH];
        #pragma unroll
        for (int h = 0; h < HH; ++h) pr[h] = 0.0f;
        float sq = 0.0f;
        #pragma unroll
        for (int j = 0; j < HH; ++j) {
            float fj = f[j];
            #pragma unroll
            for (int h = 0; h < HH; ++h) pr[h] = fmaf(fj, s_WeB[j][h], pr[h]);
            sq = fmaf(fj, fj, sq);
            s_sv[sp][j] = fj;
        }
        #pragma unroll
        for (int h = 0; h < HH; ++h) s_proj[sp][h] = pr[h];
        s_sv[sp][16] = sq;
        s_sv[sp][17] = 0.0f;
    }

    // ---- 2 tracks per thread ----
    float acc0, acc1;
    ull m0[8], m1[8];
    {
        const float* base = x_trk + (size_t)(b * NTRK + half * 256) * 8;
        mlp_pair(base + (size_t)tid * 8, base + (size_t)(tid + TPB) * 8,
                 s_W1t, s_W2t, s_b1t, s_b2t, s_wv, s_const, acc0, acc1, m0, m1);
    }
    __syncthreads();

    // ---- kNN: batch-8 top-8, 2 tracks sharing each SV row load ----
    float A0[KK], A1[KK];
    #pragma unroll
    for (int k = 0; k < KK; ++k) {
        const float inf = __int_as_float(0x7f800000);
        A0[k] = inf; A1[k] = inf;
    }

#define KEYCHAIN(M, OUT) { \
        ull a = fma2(M[0], q0.x, initv); \
        a = fma2(M[1], q0.y, a); \
        a = fma2(M[2], q1.x, a); \
        a = fma2(M[3], q1.y, a); \
        a = fma2(M[4], q2.x, a); \
        a = fma2(M[5], q2.y, a); \
        a = fma2(M[6], q3.x, a); \
        a = fma2(M[7], q3.y, a); \
        float lo_, hi_; unpack2(a, lo_, hi_); \
        OUT = __uint_as_float((__float_as_uint(lo_ + hi_) & 0xFFFFFF80u) | (unsigned)s); }

    #pragma unroll 1
    for (int g = 0; g < NSV; g += 8) {
        float c0[8], c1[8];
        #pragma unroll
        for (int i = 0; i < 8; ++i) {
            const int s = g + i;
            const ulonglong2* r = reinterpret_cast<const ulonglong2*>(s_sv[s]);
            ulonglong2 q0 = r[0], q1 = r[1], q2 = r[2], q3 = r[3];
            ull initv = reinterpret_cast<const ull*>(s_sv[s])[8];   // (ssq, 0)
            KEYCHAIN(m0, c0[i]);
            KEYCHAIN(m1, c1[i]);
        }
        sort8(c0); merge8(A0, c0);
        sort8(c1); merge8(A1, c1);
    }
#undef KEYCHAIN

    // ---- max-pool over neighbor projections + sigmoid ----
    float osum = 0.0f;
#define POOL(Aarr, accv) { \
        float pm[HH]; \
        _Pragma("unroll") \
        for (int h = 0; h < HH; ++h) pm[h] = __int_as_float(0xff800000); \
        _Pragma("unroll") \
        for (int k = 0; k < KK; ++k) { \
            int idx = (int)(__float_as_uint(Aarr[k]) & 0x7Fu); \
            const float4* pr_ = reinterpret_cast<const float4*>(s_proj[idx]); \
            const float4 p0 = pr_[0], p1 = pr_[1], p2 = pr_[2], p3 = pr_[3]; \
            pm[0]  = fmaxf(pm[0],  p0.x); pm[1]  = fmaxf(pm[1],  p0.y); \
            pm[2]  = fmaxf(pm[2],  p0.z); pm[3]  = fmaxf(pm[3],  p0.w); \
            pm[4]  = fmaxf(pm[4],  p1.x); pm[5]  = fmaxf(pm[5],  p1.y); \
            pm[6]  = fmaxf(pm[6],  p1.z); pm[7]  = fmaxf(pm[7],  p1.w); \
            pm[8]  = fmaxf(pm[8],  p2.x); pm[9]  = fmaxf(pm[9],  p2.y); \
            pm[10] = fmaxf(pm[10], p2.z); pm[11] = fmaxf(pm[11], p2.w); \
            pm[12] = fmaxf(pm[12], p3.x); pm[13] = fmaxf(pm[13], p3.y); \
            pm[14] = fmaxf(pm[14], p3.z); pm[15] = fmaxf(pm[15], p3.w); \
        } \
        float a_ = accv; \
        _Pragma("unroll") \
        for (int h = 0; h < HH; ++h) a_ = fmaf(pm[h], s_Wo[h], a_); \
        osum += 1.0f / (1.0f + __expf(-a_)); }

    POOL(A0, acc0);
    POOL(A1, acc1);
#undef POOL

    // ---- partial sum over this CTA's 256 tracks ----
    float v = osum;
    #pragma unroll
    for (int off = 16; off > 0; off >>= 1) v += __shfl_xor_sync(0xFFFFFFFFu, v, off);
    const int warp = tid >> 5;
    const int lane = tid & 31;
    if (lane == 0) s_warpsum[warp] = v;
    __syncthreads();
    if (tid == 0)
        g_partial[blockIdx.x] = s_warpsum[0] + s_warpsum[1] + s_warpsum[2] + s_warpsum[3];
}

// deterministic fixed-order combine + batch_out
__global__ void finalize_kernel(float* __restrict__ out, int out_size) {
    const int i = blockIdx.x * blockDim.x + threadIdx.x;
    if (i < BB) {
        out[i] = (g_partial[2 * i] + g_partial[2 * i + 1]) * (1.0f / (float)NTRK);
        if (BB + i < out_size) out[BB + i] = (float)i;
    }
}

extern "C" void kernel_launch(void* const* d_in, const int* in_sizes, int n_in,
                              void* d_out, int out_size) {
    const float* x_sv = (const float*)d_in[0];
    const float* x_trk = (const float*)d_in[1];
    // d_in[2] = batch_sv, d_in[3] = batch_trk : deterministic repeats, unused
    const float* W1s = (const float*)d_in[4];
    const float* b1s = (const float*)d_in[5];
    const float* W2s = (const float*)d_in[6];
    const float* b2s = (const float*)d_in[7];
    const float* W1t = (const float*)d_in[8];
    const float* b1t = (const float*)d_in[9];
    const float* W2t = (const float*)d_in[10];
    const float* b2t = (const float*)d_in[11];
    const float* We  = (const float*)d_in[12];
    const float* be  = (const float*)d_in[13];
    const float* Wo  = (const float*)d_in[14];
    const float* bo  = (const float*)d_in[15];
    float* out = (float*)d_out;

    fused_gnn_kernel<<<2 * BB, TPB>>>(x_sv, x_trk,
                                      W1s, b1s, W2s, b2s,
                                      W1t, b1t, W2t, b2t,
                                      We, be, Wo, bo);
    finalize_kernel<<<2, 256>>>(out, out_size);
}